// round 9
// baseline (speedup 1.0000x reference)
#include <cuda_runtime.h>
#include <cuda_fp16.h>

// Problem dims (fixed by reference setup_inputs)
constexpr int B_ = 8;
constexpr int T_ = 100;
constexpr int S_ = 400;
constexpr int H_ = 256;

constexpr int TGT = 2;    // t-rows per attn CTA
constexpr int NTH = 416;  // attn threads (13 warps; 400 active s-lanes)
constexpr int UF  = 8;    // wh prefetch depth

// Scratch (device globals — no allocation allowed)
__device__ float g_WhT[B_ * H_ * S_];   // (enc @ W_h + b_attn)^T : [b][h][s]
__device__ float g_Ws [B_ * T_ * H_];   // dec @ W_s
__device__ float g_Apre[B_ * T_ * S_];  // A_prelim
__device__ float g_cov [B_ * T_ * S_];  // shifted cumsum of A_prelim

// Packed tanh: one MUFU evaluates tanh for both t-rows. Inputs/accum stay f32.
__device__ __forceinline__ unsigned tanh2(unsigned x) {
    unsigned y;
    asm("tanh.approx.f16x2 %0, %1;" : "=r"(y) : "r"(x));
    return y;
}

// ---------------------------------------------------------------------------
// Fused projection GEMMs, 64x32 tiles, 256 thr, 2x4 per thread.
// blockIdx.y <  50 : WhT tile -> transposed store into g_WhT (+bias)
// blockIdx.y >= 50 : Ws  tile -> row-major store into g_Ws
// ---------------------------------------------------------------------------
__global__ __launch_bounds__(256) void dual_gemm(
    const float* __restrict__ enc, const float* __restrict__ W_h,
    const float* __restrict__ dec, const float* __restrict__ W_s,
    const float* __restrict__ bias)
{
    constexpr int K = H_, N = H_;
    bool isWh = blockIdx.y < 50;
    int  myTile = isWh ? blockIdx.y : (blockIdx.y - 50);
    int  M  = isWh ? B_ * S_ : B_ * T_;
    const float* A  = isWh ? enc : dec;
    const float* Bm = isWh ? W_h : W_s;

    int m0 = myTile * 64, n0 = blockIdx.x * 32;
    int tid = threadIdx.x;
    int tx = tid & 7;
    int ty = tid >> 3;

    __shared__ float As[16][68];
    __shared__ float Bs[16][36];
    __shared__ float Ts[32][65];

    float acc[2][4] = {};

    int lm  = tid >> 2;
    int lk4 = tid & 3;
    int bkr = tid >> 4;
    int bnc = tid & 15;

    for (int k = 0; k < K; k += 16) {
        float4 av = make_float4(0.f, 0.f, 0.f, 0.f);
        int gm = m0 + lm;
        if (gm < M) av = *(const float4*)(A + (size_t)gm * K + k + lk4 * 4);
        As[lk4 * 4 + 0][lm] = av.x;
        As[lk4 * 4 + 1][lm] = av.y;
        As[lk4 * 4 + 2][lm] = av.z;
        As[lk4 * 4 + 3][lm] = av.w;
        float2 bv = *(const float2*)(Bm + (size_t)(k + bkr) * N + n0 + bnc * 2);
        Bs[bkr][bnc * 2 + 0] = bv.x;
        Bs[bkr][bnc * 2 + 1] = bv.y;
        __syncthreads();
#pragma unroll
        for (int kk = 0; kk < 16; kk++) {
            float2 a = *(float2*)&As[kk][ty * 2];
            float4 b = *(float4*)&Bs[kk][tx * 4];
            acc[0][0] = fmaf(a.x, b.x, acc[0][0]);
            acc[0][1] = fmaf(a.x, b.y, acc[0][1]);
            acc[0][2] = fmaf(a.x, b.z, acc[0][2]);
            acc[0][3] = fmaf(a.x, b.w, acc[0][3]);
            acc[1][0] = fmaf(a.y, b.x, acc[1][0]);
            acc[1][1] = fmaf(a.y, b.y, acc[1][1]);
            acc[1][2] = fmaf(a.y, b.z, acc[1][2]);
            acc[1][3] = fmaf(a.y, b.w, acc[1][3]);
        }
        __syncthreads();
    }

    if (isWh) {
#pragma unroll
        for (int j = 0; j < 4; j++) {
            float bi = bias[n0 + tx * 4 + j];
#pragma unroll
            for (int i = 0; i < 2; i++)
                Ts[tx * 4 + j][ty * 2 + i] = acc[i][j] + bi;
        }
        __syncthreads();
#pragma unroll
        for (int kk = 0; kk < 8; kk++) {
            int e  = tid + 256 * kk;
            int h  = e >> 6;
            int sl = e & 63;
            int m  = m0 + sl;
            int b  = m / S_;
            int s  = m - b * S_;
            g_WhT[(size_t)b * H_ * S_ + (size_t)(n0 + h) * S_ + s] = Ts[h][sl];
        }
    } else {
#pragma unroll
        for (int i = 0; i < 2; i++) {
            int gm = m0 + ty * 2 + i;
            if (gm < M) {
#pragma unroll
                for (int j = 0; j < 4; j++)
                    g_Ws[(size_t)gm * N + n0 + tx * 4 + j] = acc[i][j];
            }
        }
    }
}

// ---------------------------------------------------------------------------
// Batched SGEMM, 32x32 tile, 2x2 per thread (context).
// ---------------------------------------------------------------------------
__global__ __launch_bounds__(256) void sgemm32(
    const float* __restrict__ A, const float* __restrict__ Bm,
    float* __restrict__ C, int M, int N, int K,
    long long sA, long long sB, long long sC)
{
    int bz = blockIdx.z;
    A  += (size_t)bz * sA;
    Bm += (size_t)bz * sB;
    C  += (size_t)bz * sC;

    int m0 = blockIdx.y * 32, n0 = blockIdx.x * 32;
    int tid = threadIdx.x;
    int tx = tid & 15, ty = tid >> 4;

    __shared__ float As[32][17];
    __shared__ float Bs[16][33];

    float c00 = 0.f, c01 = 0.f, c10 = 0.f, c11 = 0.f;

    for (int k = 0; k < K; k += 16) {
#pragma unroll
        for (int i = 0; i < 2; i++) {
            int e = tid + i * 256;
            int m = e >> 4, kk = e & 15;
            int gm = m0 + m;
            As[m][kk] = (gm < M) ? A[(size_t)gm * K + k + kk] : 0.f;
            int kk2 = e >> 5, n = e & 31;
            Bs[kk2][n] = Bm[(size_t)(k + kk2) * N + n0 + n];
        }
        __syncthreads();
#pragma unroll
        for (int kk = 0; kk < 16; kk++) {
            float a0 = As[ty][kk], a1 = As[ty + 16][kk];
            float b0 = Bs[kk][tx], b1 = Bs[kk][tx + 16];
            c00 = fmaf(a0, b0, c00);
            c01 = fmaf(a0, b1, c01);
            c10 = fmaf(a1, b0, c10);
            c11 = fmaf(a1, b1, c11);
        }
        __syncthreads();
    }

    if (m0 + ty < M) {
        C[(size_t)(m0 + ty) * N + n0 + tx]      = c00;
        C[(size_t)(m0 + ty) * N + n0 + tx + 16] = c01;
    }
    if (m0 + ty + 16 < M) {
        C[(size_t)(m0 + ty + 16) * N + n0 + tx]      = c10;
        C[(size_t)(m0 + ty + 16) * N + n0 + tx + 16] = c11;
    }
}

// ---------------------------------------------------------------------------
// attn_pass: lane-per-s over WhT, f16x2 tanh, software-pipelined UF-deep
// wh prefetch (double buffer) to expose LDG MLP. 416 threads.
// ---------------------------------------------------------------------------
template <bool PASS2>
__global__ __launch_bounds__(NTH) void attn_pass(
    const unsigned char* __restrict__ mask,
    const float* __restrict__ v,
    const float* __restrict__ wc,
    float* __restrict__ AoutParam,
    float* __restrict__ loss)
{
    __shared__ float2 sVW[H_];        // (v[h], wc[h])
    __shared__ float2 sWp[H_];        // (ws_t0[h], ws_t1[h])
    __shared__ float  sE[TGT][S_];
    __shared__ float  sCov[TGT][S_];
    __shared__ float  sRed[16];

    int tid = threadIdx.x;
    int b   = blockIdx.x / (T_ / TGT);
    int t0  = (blockIdx.x % (T_ / TGT)) * TGT;

    const float* ws0 = g_Ws + ((size_t)b * T_ + t0) * H_;
    for (int h = tid; h < H_; h += NTH) {
        sVW[h] = make_float2(v[h], PASS2 ? wc[h] : 0.f);
        sWp[h] = make_float2(ws0[h], ws0[H_ + h]);
    }
    if (PASS2) {
        const float* cv = g_cov + ((size_t)b * T_ + t0) * S_;
        float* flat = &sCov[0][0];
        for (int i = tid; i < TGT * S_; i += NTH) flat[i] = cv[i];
    }
    __syncthreads();

    int s = tid;
    if (s < S_) {
        const float* whp = g_WhT + (size_t)b * H_ * S_ + s;
        bool mk = mask[b * S_ + s] != 0;
        float c0 = 0.f, c1 = 0.f;
        if (PASS2) { c0 = sCov[0][s]; c1 = sCov[1][s]; }
        float acc0 = 0.f, acc1 = 0.f;

        // software pipeline: buf holds wh[h0..h0+UF), nxt prefetches next group
        float buf[UF];
#pragma unroll
        for (int i = 0; i < UF; i++) buf[i] = __ldg(whp + (size_t)i * S_);

#pragma unroll
        for (int h0 = 0; h0 < H_; h0 += UF) {
            float nxt[UF];
            if (h0 + UF < H_) {
#pragma unroll
                for (int i = 0; i < UF; i++)
                    nxt[i] = __ldg(whp + (size_t)(h0 + UF + i) * S_);
            }
#pragma unroll
            for (int i = 0; i < UF; i++) {
                int h = h0 + i;
                float2 vw = sVW[h];
                float2 wp = sWp[h];
                float x0 = buf[i] + wp.x;
                float x1 = buf[i] + wp.y;
                if (PASS2) {
                    x0 = fmaf(c0, vw.y, x0);
                    x1 = fmaf(c1, vw.y, x1);
                }
                __half2 xh = __floats2half2_rn(x0, x1);
                unsigned th = tanh2(*(unsigned*)&xh);
                __half2 t2 = *(__half2*)&th;
                acc0 = fmaf(vw.x, __low2float(t2),  acc0);
                acc1 = fmaf(vw.x, __high2float(t2), acc1);
            }
            if (h0 + UF < H_) {
#pragma unroll
                for (int i = 0; i < UF; i++) buf[i] = nxt[i];
            }
        }

        float e0 = fminf(fmaxf(acc0, -30.0f), 30.0f);
        float e1 = fminf(fmaxf(acc1, -30.0f), 30.0f);
        sE[0][s] = mk ? -1e30f : e0;
        sE[1][s] = mk ? -1e30f : e1;
    }
    __syncthreads();

    int lane = tid & 31, wid = tid >> 5;  // 13 warps
    float lossAcc = 0.f;

#pragma unroll
    for (int r = 0; r < TGT; r++) {
        float m = (tid < S_) ? sE[r][tid] : -1e30f;
#pragma unroll
        for (int o = 16; o; o >>= 1) m = fmaxf(m, __shfl_xor_sync(0xffffffffu, m, o));
        if (lane == 0) sRed[wid] = m;
        __syncthreads();
        if (wid == 0) {
            float mm = (lane < 13) ? sRed[lane] : -1e30f;
#pragma unroll
            for (int o = 16; o; o >>= 1) mm = fmaxf(mm, __shfl_xor_sync(0xffffffffu, mm, o));
            if (lane == 0) sRed[14] = mm;
        }
        __syncthreads();
        float rowMax = sRed[14];

        float ex = (tid < S_) ? __expf(sE[r][tid] - rowMax) : 0.f;
        float sum = ex;
#pragma unroll
        for (int o = 16; o; o >>= 1) sum += __shfl_xor_sync(0xffffffffu, sum, o);
        if (lane == 0) sRed[wid] = sum;
        __syncthreads();
        if (wid == 0) {
            float ss = (lane < 13) ? sRed[lane] : 0.f;
#pragma unroll
            for (int o = 16; o; o >>= 1) ss += __shfl_xor_sync(0xffffffffu, ss, o);
            if (lane == 0) sRed[15] = ss;
        }
        __syncthreads();
        float inv = 1.0f / fmaxf(sRed[15], 1e-30f);

        if (tid < S_) {
            float a = ex * inv;
            size_t rowOff = ((size_t)b * T_ + t0 + r) * S_;
            (PASS2 ? AoutParam : g_Apre)[rowOff + tid] = a;
            if (PASS2) lossAcc += fminf(a, sCov[r][tid]);
        }
        __syncthreads();
    }

    if (PASS2) {
#pragma unroll
        for (int o = 16; o; o >>= 1) lossAcc += __shfl_xor_sync(0xffffffffu, lossAcc, o);
        if (lane == 0) sRed[wid] = lossAcc;
        __syncthreads();
        if (tid == 0) {
            float p = 0.f;
#pragma unroll
            for (int i = 0; i < 13; i++) p += sRed[i];
            atomicAdd(loss, p * (1.0f / (B_ * T_)));
        }
    }
}

// ---------------------------------------------------------------------------
// cumsum: CTA = (b, 32 s-lanes); 128 threads = 32 s x 4 t-groups of 25.
// ---------------------------------------------------------------------------
__global__ __launch_bounds__(128) void cumsum_k(float* __restrict__ loss)
{
    constexpr int TSEG = 25;
    __shared__ float tot[4][32];

    if (blockIdx.x == 0 && blockIdx.y == 0 && threadIdx.x == 0) *loss = 0.f;

    int g  = threadIdx.x >> 5;
    int sl = threadIdx.x & 31;
    int s  = blockIdx.x * 32 + sl;
    int b  = blockIdx.y;
    bool act = (s < S_);

    size_t base = (size_t)b * T_ * S_ + s;
    float vals[TSEG];
    if (act) {
#pragma unroll
        for (int u = 0; u < TSEG; u++)
            vals[u] = g_Apre[base + (size_t)(g * TSEG + u) * S_];
    } else {
#pragma unroll
        for (int u = 0; u < TSEG; u++) vals[u] = 0.f;
    }

    float run = 0.f;
#pragma unroll
    for (int u = 0; u < TSEG; u++) {
        float x = vals[u];
        vals[u] = run;
        run += x;
    }
    tot[g][sl] = run;
    __syncthreads();

    float off = 0.f;
#pragma unroll
    for (int gg = 0; gg < 3; gg++)
        if (gg < g) off += tot[gg][sl];

    if (act) {
#pragma unroll
        for (int u = 0; u < TSEG; u++)
            g_cov[base + (size_t)(g * TSEG + u) * S_] = off + vals[u];
    }
}

// ---------------------------------------------------------------------------
extern "C" void kernel_launch(void* const* d_in, const int* in_sizes, int n_in,
                              void* d_out, int out_size)
{
    const float*         dec    = (const float*)d_in[0];
    const float*         enc    = (const float*)d_in[1];
    const unsigned char* mask   = (const unsigned char*)d_in[2];
    const float*         W_h    = (const float*)d_in[3];
    const float*         W_s    = (const float*)d_in[4];
    const float*         w_c    = (const float*)d_in[5];
    const float*         v      = (const float*)d_in[6];
    const float*         b_attn = (const float*)d_in[7];

    float* out  = (float*)d_out;
    float* ctx  = out;
    float* Afin = out + (size_t)B_ * T_ * H_;
    float* loss = Afin + (size_t)B_ * T_ * S_;

    // Fused projections: 50 WhT tiles + 13 Ws tiles -> grid (8, 63)
    dual_gemm<<<dim3(H_ / 32, 63), 256>>>(enc, W_h, dec, W_s, b_attn);

    // Pass 1: A_prelim
    attn_pass<false><<<B_ * (T_ / TGT), NTH>>>(mask, v, nullptr, nullptr, nullptr);

    // Shifted cumsum over t (also zeroes loss slot)
    cumsum_k<<<dim3((S_ + 31) / 32, B_), 128>>>(loss);

    // Pass 2: A_final + cov_loss
    attn_pass<true><<<B_ * (T_ / TGT), NTH>>>(mask, v, w_c, Afin, loss);

    // context[b] = A_final[b] @ enc[b]
    sgemm32<<<dim3(H_ / 32, (T_ + 31) / 32, B_), 256>>>(
        Afin, enc, ctx, T_, H_, S_,
        (long long)T_ * S_, (long long)S_ * H_, (long long)T_ * H_);
}

// round 10
// speedup vs baseline: 2.7906x; 2.7906x over previous
#include <cuda_runtime.h>
#include <cuda_fp16.h>

// Problem dims (fixed by reference setup_inputs)
constexpr int B_ = 8;
constexpr int T_ = 100;
constexpr int S_ = 400;
constexpr int H_ = 256;

constexpr int TGT = 2;    // t-rows per attn CTA
constexpr int NTH = 416;  // attn threads (13 warps; 400 active s-lanes)

// Scratch (device globals — no allocation allowed)
__device__ float g_WhT[B_ * H_ * S_];   // (enc @ W_h + b_attn)^T : [b][h][s]
__device__ float g_Ws [B_ * T_ * H_];   // dec @ W_s
__device__ float g_Apre[B_ * T_ * S_];  // A_prelim
__device__ float g_cov [B_ * T_ * S_];  // shifted cumsum of A_prelim

// Packed tanh: one MUFU evaluates tanh for both t-rows. Inputs/accum stay f32.
__device__ __forceinline__ unsigned tanh2(unsigned x) {
    unsigned y;
    asm("tanh.approx.f16x2 %0, %1;" : "=r"(y) : "r"(x));
    return y;
}

// ---------------------------------------------------------------------------
// Fused projection GEMMs, 64x32 tiles, 256 thr, 2x4 per thread.
// blockIdx.y <  50 : WhT tile -> transposed store into g_WhT (+bias)
// blockIdx.y >= 50 : Ws  tile -> row-major store into g_Ws
// ---------------------------------------------------------------------------
__global__ __launch_bounds__(256) void dual_gemm(
    const float* __restrict__ enc, const float* __restrict__ W_h,
    const float* __restrict__ dec, const float* __restrict__ W_s,
    const float* __restrict__ bias)
{
    constexpr int K = H_, N = H_;
    bool isWh = blockIdx.y < 50;
    int  myTile = isWh ? blockIdx.y : (blockIdx.y - 50);
    int  M  = isWh ? B_ * S_ : B_ * T_;
    const float* A  = isWh ? enc : dec;
    const float* Bm = isWh ? W_h : W_s;

    int m0 = myTile * 64, n0 = blockIdx.x * 32;
    int tid = threadIdx.x;
    int tx = tid & 7;
    int ty = tid >> 3;

    __shared__ float As[16][68];
    __shared__ float Bs[16][36];
    __shared__ float Ts[32][65];

    float acc[2][4] = {};

    int lm  = tid >> 2;
    int lk4 = tid & 3;
    int bkr = tid >> 4;
    int bnc = tid & 15;

    for (int k = 0; k < K; k += 16) {
        float4 av = make_float4(0.f, 0.f, 0.f, 0.f);
        int gm = m0 + lm;
        if (gm < M) av = *(const float4*)(A + (size_t)gm * K + k + lk4 * 4);
        As[lk4 * 4 + 0][lm] = av.x;
        As[lk4 * 4 + 1][lm] = av.y;
        As[lk4 * 4 + 2][lm] = av.z;
        As[lk4 * 4 + 3][lm] = av.w;
        float2 bv = *(const float2*)(Bm + (size_t)(k + bkr) * N + n0 + bnc * 2);
        Bs[bkr][bnc * 2 + 0] = bv.x;
        Bs[bkr][bnc * 2 + 1] = bv.y;
        __syncthreads();
#pragma unroll
        for (int kk = 0; kk < 16; kk++) {
            float2 a = *(float2*)&As[kk][ty * 2];
            float4 b = *(float4*)&Bs[kk][tx * 4];
            acc[0][0] = fmaf(a.x, b.x, acc[0][0]);
            acc[0][1] = fmaf(a.x, b.y, acc[0][1]);
            acc[0][2] = fmaf(a.x, b.z, acc[0][2]);
            acc[0][3] = fmaf(a.x, b.w, acc[0][3]);
            acc[1][0] = fmaf(a.y, b.x, acc[1][0]);
            acc[1][1] = fmaf(a.y, b.y, acc[1][1]);
            acc[1][2] = fmaf(a.y, b.z, acc[1][2]);
            acc[1][3] = fmaf(a.y, b.w, acc[1][3]);
        }
        __syncthreads();
    }

    if (isWh) {
#pragma unroll
        for (int j = 0; j < 4; j++) {
            float bi = bias[n0 + tx * 4 + j];
#pragma unroll
            for (int i = 0; i < 2; i++)
                Ts[tx * 4 + j][ty * 2 + i] = acc[i][j] + bi;
        }
        __syncthreads();
#pragma unroll
        for (int kk = 0; kk < 8; kk++) {
            int e  = tid + 256 * kk;
            int h  = e >> 6;
            int sl = e & 63;
            int m  = m0 + sl;
            int b  = m / S_;
            int s  = m - b * S_;
            g_WhT[(size_t)b * H_ * S_ + (size_t)(n0 + h) * S_ + s] = Ts[h][sl];
        }
    } else {
#pragma unroll
        for (int i = 0; i < 2; i++) {
            int gm = m0 + ty * 2 + i;
            if (gm < M) {
#pragma unroll
                for (int j = 0; j < 4; j++)
                    g_Ws[(size_t)gm * N + n0 + tx * 4 + j] = acc[i][j];
            }
        }
    }
}

// ---------------------------------------------------------------------------
// Batched SGEMM, 32x32 tile, 2x2 per thread (context).
// ---------------------------------------------------------------------------
__global__ __launch_bounds__(256) void sgemm32(
    const float* __restrict__ A, const float* __restrict__ Bm,
    float* __restrict__ C, int M, int N, int K,
    long long sA, long long sB, long long sC)
{
    int bz = blockIdx.z;
    A  += (size_t)bz * sA;
    Bm += (size_t)bz * sB;
    C  += (size_t)bz * sC;

    int m0 = blockIdx.y * 32, n0 = blockIdx.x * 32;
    int tid = threadIdx.x;
    int tx = tid & 15, ty = tid >> 4;

    __shared__ float As[32][17];
    __shared__ float Bs[16][33];

    float c00 = 0.f, c01 = 0.f, c10 = 0.f, c11 = 0.f;

    for (int k = 0; k < K; k += 16) {
#pragma unroll
        for (int i = 0; i < 2; i++) {
            int e = tid + i * 256;
            int m = e >> 4, kk = e & 15;
            int gm = m0 + m;
            As[m][kk] = (gm < M) ? A[(size_t)gm * K + k + kk] : 0.f;
            int kk2 = e >> 5, n = e & 31;
            Bs[kk2][n] = Bm[(size_t)(k + kk2) * N + n0 + n];
        }
        __syncthreads();
#pragma unroll
        for (int kk = 0; kk < 16; kk++) {
            float a0 = As[ty][kk], a1 = As[ty + 16][kk];
            float b0 = Bs[kk][tx], b1 = Bs[kk][tx + 16];
            c00 = fmaf(a0, b0, c00);
            c01 = fmaf(a0, b1, c01);
            c10 = fmaf(a1, b0, c10);
            c11 = fmaf(a1, b1, c11);
        }
        __syncthreads();
    }

    if (m0 + ty < M) {
        C[(size_t)(m0 + ty) * N + n0 + tx]      = c00;
        C[(size_t)(m0 + ty) * N + n0 + tx + 16] = c01;
    }
    if (m0 + ty + 16 < M) {
        C[(size_t)(m0 + ty + 16) * N + n0 + tx]      = c10;
        C[(size_t)(m0 + ty + 16) * N + n0 + tx + 16] = c11;
    }
}

// ---------------------------------------------------------------------------
// attn_pass: lane-per-s over WhT, f16x2 tanh, scalar rotating prefetch
// (depth 4) with explicit reg budget via __launch_bounds__(NTH, 3).
// ---------------------------------------------------------------------------
template <bool PASS2>
__global__ __launch_bounds__(NTH, 3) void attn_pass(
    const unsigned char* __restrict__ mask,
    const float* __restrict__ v,
    const float* __restrict__ wc,
    float* __restrict__ AoutParam,
    float* __restrict__ loss)
{
    __shared__ float2 sVW[H_];        // (v[h], wc[h])
    __shared__ float2 sWp[H_];        // (ws_t0[h], ws_t1[h])
    __shared__ float  sE[TGT][S_];
    __shared__ float  sCov[TGT][S_];
    __shared__ float  sRed[16];

    int tid = threadIdx.x;
    int b   = blockIdx.x / (T_ / TGT);
    int t0  = (blockIdx.x % (T_ / TGT)) * TGT;

    const float* ws0 = g_Ws + ((size_t)b * T_ + t0) * H_;
    for (int h = tid; h < H_; h += NTH) {
        sVW[h] = make_float2(v[h], PASS2 ? wc[h] : 0.f);
        sWp[h] = make_float2(ws0[h], ws0[H_ + h]);
    }
    if (PASS2) {
        const float* cv = g_cov + ((size_t)b * T_ + t0) * S_;
        float* flat = &sCov[0][0];
        for (int i = tid; i < TGT * S_; i += NTH) flat[i] = cv[i];
    }
    __syncthreads();

    int s = tid;
    if (s < S_) {
        const float* whp = g_WhT + (size_t)b * H_ * S_ + s;
        bool mk = mask[b * S_ + s] != 0;
        float c0 = 0.f, c1 = 0.f;
        if (PASS2) { c0 = sCov[0][s]; c1 = sCov[1][s]; }
        float acc0 = 0.f, acc1 = 0.f;

        // rotating scalar prefetch, depth 4 (8 extra live floats max)
        float p0 = __ldg(whp);
        float p1 = __ldg(whp + S_);
        float p2 = __ldg(whp + 2 * S_);
        float p3 = __ldg(whp + 3 * S_);

#pragma unroll 2
        for (int h0 = 0; h0 < H_; h0 += 4) {
            float n0 = 0.f, n1 = 0.f, n2 = 0.f, n3 = 0.f;
            if (h0 + 4 < H_) {
                const float* q = whp + (size_t)(h0 + 4) * S_;
                n0 = __ldg(q);
                n1 = __ldg(q + S_);
                n2 = __ldg(q + 2 * S_);
                n3 = __ldg(q + 3 * S_);
            }
#pragma unroll
            for (int i = 0; i < 4; i++) {
                float whv = (i == 0) ? p0 : (i == 1) ? p1 : (i == 2) ? p2 : p3;
                int h = h0 + i;
                float2 vw = sVW[h];
                float2 wp = sWp[h];
                float x0 = whv + wp.x;
                float x1 = whv + wp.y;
                if (PASS2) {
                    x0 = fmaf(c0, vw.y, x0);
                    x1 = fmaf(c1, vw.y, x1);
                }
                __half2 xh = __floats2half2_rn(x0, x1);
                unsigned th = tanh2(*(unsigned*)&xh);
                __half2 t2 = *(__half2*)&th;
                acc0 = fmaf(vw.x, __low2float(t2),  acc0);
                acc1 = fmaf(vw.x, __high2float(t2), acc1);
            }
            p0 = n0; p1 = n1; p2 = n2; p3 = n3;
        }

        float e0 = fminf(fmaxf(acc0, -30.0f), 30.0f);
        float e1 = fminf(fmaxf(acc1, -30.0f), 30.0f);
        sE[0][s] = mk ? -1e30f : e0;
        sE[1][s] = mk ? -1e30f : e1;
    }
    __syncthreads();

    int lane = tid & 31, wid = tid >> 5;  // 13 warps
    float lossAcc = 0.f;

#pragma unroll
    for (int r = 0; r < TGT; r++) {
        float m = (tid < S_) ? sE[r][tid] : -1e30f;
#pragma unroll
        for (int o = 16; o; o >>= 1) m = fmaxf(m, __shfl_xor_sync(0xffffffffu, m, o));
        if (lane == 0) sRed[wid] = m;
        __syncthreads();
        if (wid == 0) {
            float mm = (lane < 13) ? sRed[lane] : -1e30f;
#pragma unroll
            for (int o = 16; o; o >>= 1) mm = fmaxf(mm, __shfl_xor_sync(0xffffffffu, mm, o));
            if (lane == 0) sRed[14] = mm;
        }
        __syncthreads();
        float rowMax = sRed[14];

        float ex = (tid < S_) ? __expf(sE[r][tid] - rowMax) : 0.f;
        float sum = ex;
#pragma unroll
        for (int o = 16; o; o >>= 1) sum += __shfl_xor_sync(0xffffffffu, sum, o);
        if (lane == 0) sRed[wid] = sum;
        __syncthreads();
        if (wid == 0) {
            float ss = (lane < 13) ? sRed[lane] : 0.f;
#pragma unroll
            for (int o = 16; o; o >>= 1) ss += __shfl_xor_sync(0xffffffffu, ss, o);
            if (lane == 0) sRed[15] = ss;
        }
        __syncthreads();
        float inv = 1.0f / fmaxf(sRed[15], 1e-30f);

        if (tid < S_) {
            float a = ex * inv;
            size_t rowOff = ((size_t)b * T_ + t0 + r) * S_;
            (PASS2 ? AoutParam : g_Apre)[rowOff + tid] = a;
            if (PASS2) lossAcc += fminf(a, sCov[r][tid]);
        }
        __syncthreads();
    }

    if (PASS2) {
#pragma unroll
        for (int o = 16; o; o >>= 1) lossAcc += __shfl_xor_sync(0xffffffffu, lossAcc, o);
        if (lane == 0) sRed[wid] = lossAcc;
        __syncthreads();
        if (tid == 0) {
            float p = 0.f;
#pragma unroll
            for (int i = 0; i < 13; i++) p += sRed[i];
            atomicAdd(loss, p * (1.0f / (B_ * T_)));
        }
    }
}

// ---------------------------------------------------------------------------
// cumsum: CTA = (b, 32 s-lanes); 128 threads = 32 s x 4 t-groups of 25.
// ---------------------------------------------------------------------------
__global__ __launch_bounds__(128) void cumsum_k(float* __restrict__ loss)
{
    constexpr int TSEG = 25;
    __shared__ float tot[4][32];

    if (blockIdx.x == 0 && blockIdx.y == 0 && threadIdx.x == 0) *loss = 0.f;

    int g  = threadIdx.x >> 5;
    int sl = threadIdx.x & 31;
    int s  = blockIdx.x * 32 + sl;
    int b  = blockIdx.y;
    bool act = (s < S_);

    size_t base = (size_t)b * T_ * S_ + s;
    float vals[TSEG];
    if (act) {
#pragma unroll
        for (int u = 0; u < TSEG; u++)
            vals[u] = g_Apre[base + (size_t)(g * TSEG + u) * S_];
    } else {
#pragma unroll
        for (int u = 0; u < TSEG; u++) vals[u] = 0.f;
    }

    float run = 0.f;
#pragma unroll
    for (int u = 0; u < TSEG; u++) {
        float x = vals[u];
        vals[u] = run;
        run += x;
    }
    tot[g][sl] = run;
    __syncthreads();

    float off = 0.f;
#pragma unroll
    for (int gg = 0; gg < 3; gg++)
        if (gg < g) off += tot[gg][sl];

    if (act) {
#pragma unroll
        for (int u = 0; u < TSEG; u++)
            g_cov[base + (size_t)(g * TSEG + u) * S_] = off + vals[u];
    }
}

// ---------------------------------------------------------------------------
extern "C" void kernel_launch(void* const* d_in, const int* in_sizes, int n_in,
                              void* d_out, int out_size)
{
    const float*         dec    = (const float*)d_in[0];
    const float*         enc    = (const float*)d_in[1];
    const unsigned char* mask   = (const unsigned char*)d_in[2];
    const float*         W_h    = (const float*)d_in[3];
    const float*         W_s    = (const float*)d_in[4];
    const float*         w_c    = (const float*)d_in[5];
    const float*         v      = (const float*)d_in[6];
    const float*         b_attn = (const float*)d_in[7];

    float* out  = (float*)d_out;
    float* ctx  = out;
    float* Afin = out + (size_t)B_ * T_ * H_;
    float* loss = Afin + (size_t)B_ * T_ * S_;

    // Fused projections: 50 WhT tiles + 13 Ws tiles -> grid (8, 63)
    dual_gemm<<<dim3(H_ / 32, 63), 256>>>(enc, W_h, dec, W_s, b_attn);

    // Pass 1: A_prelim
    attn_pass<false><<<B_ * (T_ / TGT), NTH>>>(mask, v, nullptr, nullptr, nullptr);

    // Shifted cumsum over t (also zeroes loss slot)
    cumsum_k<<<dim3((S_ + 31) / 32, B_), 128>>>(loss);

    // Pass 2: A_final + cov_loss
    attn_pass<true><<<B_ * (T_ / TGT), NTH>>>(mask, v, w_c, Afin, loss);

    // context[b] = A_final[b] @ enc[b]
    sgemm32<<<dim3(H_ / 32, (T_ + 31) / 32, B_), 256>>>(
        Afin, enc, ctx, T_, H_, S_,
        (long long)T_ * S_, (long long)S_ * H_, (long long)T_ * H_);
}

// round 11
// speedup vs baseline: 2.8790x; 1.0316x over previous
#include <cuda_runtime.h>
#include <cuda_fp16.h>

// Problem dims (fixed by reference setup_inputs)
constexpr int B_ = 8;
constexpr int T_ = 100;
constexpr int S_ = 400;
constexpr int H_ = 256;

constexpr int TGT = 2;    // t-rows per attn CTA
constexpr int NTH = 416;  // attn threads (13 warps; 400 active s-lanes)

// Scratch (device globals — no allocation allowed)
__device__ float g_WhT[B_ * H_ * S_];   // (enc @ W_h + b_attn)^T : [b][h][s]
__device__ float g_Ws [B_ * T_ * H_];   // dec @ W_s
__device__ float g_Apre[B_ * T_ * S_];  // A_prelim
__device__ float g_cov [B_ * T_ * S_];  // shifted cumsum of A_prelim

// Packed tanh: one MUFU evaluates tanh for both t-rows. Inputs/accum stay f32.
__device__ __forceinline__ unsigned tanh2(unsigned x) {
    unsigned y;
    asm("tanh.approx.f16x2 %0, %1;" : "=r"(y) : "r"(x));
    return y;
}

// ---------------------------------------------------------------------------
// Fused projection GEMMs, 64x32 tiles, 256 thr, 2x4 per thread.
// blockIdx.y <  50 : WhT tile -> transposed store into g_WhT (+bias)
// blockIdx.y >= 50 : Ws  tile -> row-major store into g_Ws
// ---------------------------------------------------------------------------
__global__ __launch_bounds__(256) void dual_gemm(
    const float* __restrict__ enc, const float* __restrict__ W_h,
    const float* __restrict__ dec, const float* __restrict__ W_s,
    const float* __restrict__ bias)
{
    constexpr int K = H_, N = H_;
    bool isWh = blockIdx.y < 50;
    int  myTile = isWh ? blockIdx.y : (blockIdx.y - 50);
    int  M  = isWh ? B_ * S_ : B_ * T_;
    const float* A  = isWh ? enc : dec;
    const float* Bm = isWh ? W_h : W_s;

    int m0 = myTile * 64, n0 = blockIdx.x * 32;
    int tid = threadIdx.x;
    int tx = tid & 7;
    int ty = tid >> 3;

    __shared__ float As[16][68];
    __shared__ float Bs[16][36];
    __shared__ float Ts[32][65];

    float acc[2][4] = {};

    int lm  = tid >> 2;
    int lk4 = tid & 3;
    int bkr = tid >> 4;
    int bnc = tid & 15;

    for (int k = 0; k < K; k += 16) {
        float4 av = make_float4(0.f, 0.f, 0.f, 0.f);
        int gm = m0 + lm;
        if (gm < M) av = *(const float4*)(A + (size_t)gm * K + k + lk4 * 4);
        As[lk4 * 4 + 0][lm] = av.x;
        As[lk4 * 4 + 1][lm] = av.y;
        As[lk4 * 4 + 2][lm] = av.z;
        As[lk4 * 4 + 3][lm] = av.w;
        float2 bv = *(const float2*)(Bm + (size_t)(k + bkr) * N + n0 + bnc * 2);
        Bs[bkr][bnc * 2 + 0] = bv.x;
        Bs[bkr][bnc * 2 + 1] = bv.y;
        __syncthreads();
#pragma unroll
        for (int kk = 0; kk < 16; kk++) {
            float2 a = *(float2*)&As[kk][ty * 2];
            float4 b = *(float4*)&Bs[kk][tx * 4];
            acc[0][0] = fmaf(a.x, b.x, acc[0][0]);
            acc[0][1] = fmaf(a.x, b.y, acc[0][1]);
            acc[0][2] = fmaf(a.x, b.z, acc[0][2]);
            acc[0][3] = fmaf(a.x, b.w, acc[0][3]);
            acc[1][0] = fmaf(a.y, b.x, acc[1][0]);
            acc[1][1] = fmaf(a.y, b.y, acc[1][1]);
            acc[1][2] = fmaf(a.y, b.z, acc[1][2]);
            acc[1][3] = fmaf(a.y, b.w, acc[1][3]);
        }
        __syncthreads();
    }

    if (isWh) {
#pragma unroll
        for (int j = 0; j < 4; j++) {
            float bi = bias[n0 + tx * 4 + j];
#pragma unroll
            for (int i = 0; i < 2; i++)
                Ts[tx * 4 + j][ty * 2 + i] = acc[i][j] + bi;
        }
        __syncthreads();
#pragma unroll
        for (int kk = 0; kk < 8; kk++) {
            int e  = tid + 256 * kk;
            int h  = e >> 6;
            int sl = e & 63;
            int m  = m0 + sl;
            int b  = m / S_;
            int s  = m - b * S_;
            g_WhT[(size_t)b * H_ * S_ + (size_t)(n0 + h) * S_ + s] = Ts[h][sl];
        }
    } else {
#pragma unroll
        for (int i = 0; i < 2; i++) {
            int gm = m0 + ty * 2 + i;
            if (gm < M) {
#pragma unroll
                for (int j = 0; j < 4; j++)
                    g_Ws[(size_t)gm * N + n0 + tx * 4 + j] = acc[i][j];
            }
        }
    }
}

// ---------------------------------------------------------------------------
// Batched SGEMM, 32x32 tile, 2x2 per thread (context).
// ---------------------------------------------------------------------------
__global__ __launch_bounds__(256) void sgemm32(
    const float* __restrict__ A, const float* __restrict__ Bm,
    float* __restrict__ C, int M, int N, int K,
    long long sA, long long sB, long long sC)
{
    int bz = blockIdx.z;
    A  += (size_t)bz * sA;
    Bm += (size_t)bz * sB;
    C  += (size_t)bz * sC;

    int m0 = blockIdx.y * 32, n0 = blockIdx.x * 32;
    int tid = threadIdx.x;
    int tx = tid & 15, ty = tid >> 4;

    __shared__ float As[32][17];
    __shared__ float Bs[16][33];

    float c00 = 0.f, c01 = 0.f, c10 = 0.f, c11 = 0.f;

    for (int k = 0; k < K; k += 16) {
#pragma unroll
        for (int i = 0; i < 2; i++) {
            int e = tid + i * 256;
            int m = e >> 4, kk = e & 15;
            int gm = m0 + m;
            As[m][kk] = (gm < M) ? A[(size_t)gm * K + k + kk] : 0.f;
            int kk2 = e >> 5, n = e & 31;
            Bs[kk2][n] = Bm[(size_t)(k + kk2) * N + n0 + n];
        }
        __syncthreads();
#pragma unroll
        for (int kk = 0; kk < 16; kk++) {
            float a0 = As[ty][kk], a1 = As[ty + 16][kk];
            float b0 = Bs[kk][tx], b1 = Bs[kk][tx + 16];
            c00 = fmaf(a0, b0, c00);
            c01 = fmaf(a0, b1, c01);
            c10 = fmaf(a1, b0, c10);
            c11 = fmaf(a1, b1, c11);
        }
        __syncthreads();
    }

    if (m0 + ty < M) {
        C[(size_t)(m0 + ty) * N + n0 + tx]      = c00;
        C[(size_t)(m0 + ty) * N + n0 + tx + 16] = c01;
    }
    if (m0 + ty + 16 < M) {
        C[(size_t)(m0 + ty + 16) * N + n0 + tx]      = c10;
        C[(size_t)(m0 + ty + 16) * N + n0 + tx + 16] = c11;
    }
}

// ---------------------------------------------------------------------------
// attn_pass v6: R10 mainloop (depth-4 scalar prefetch, f16x2 tanh) +
// register-resident softmax: fixed max=30 (logits clipped to +-30 so
// exp(e-30) is exact and safe), ex kept in regs, cov via direct LDG.
// No sE/sCov smem, 2 syncthreads in the softmax.
// ---------------------------------------------------------------------------
template <bool PASS2>
__global__ __launch_bounds__(NTH, 3) void attn_pass(
    const unsigned char* __restrict__ mask,
    const float* __restrict__ v,
    const float* __restrict__ wc,
    float* __restrict__ AoutParam,
    float* __restrict__ loss)
{
    __shared__ float2 sVW[H_];        // (v[h], wc[h])
    __shared__ float2 sWp[H_];        // (ws_t0[h], ws_t1[h])
    __shared__ float  sRed[48];

    int tid = threadIdx.x;
    int b   = blockIdx.x / (T_ / TGT);
    int t0  = (blockIdx.x % (T_ / TGT)) * TGT;

    const float* ws0 = g_Ws + ((size_t)b * T_ + t0) * H_;
    for (int h = tid; h < H_; h += NTH) {
        sVW[h] = make_float2(v[h], PASS2 ? wc[h] : 0.f);
        sWp[h] = make_float2(ws0[h], ws0[H_ + h]);
    }
    __syncthreads();

    size_t row0 = ((size_t)b * T_ + t0) * S_;
    size_t row1 = row0 + S_;

    int s = tid;
    float ex0 = 0.f, ex1 = 0.f;
    float c0 = 0.f, c1 = 0.f;
    if (s < S_) {
        const float* whp = g_WhT + (size_t)b * H_ * S_ + s;
        bool mk = mask[b * S_ + s] != 0;
        if (PASS2) { c0 = g_cov[row0 + s]; c1 = g_cov[row1 + s]; }
        float acc0 = 0.f, acc1 = 0.f;

        // rotating scalar prefetch, depth 4 (proven R10 mainloop)
        float p0 = __ldg(whp);
        float p1 = __ldg(whp + S_);
        float p2 = __ldg(whp + 2 * S_);
        float p3 = __ldg(whp + 3 * S_);

#pragma unroll 2
        for (int h0 = 0; h0 < H_; h0 += 4) {
            float n0 = 0.f, n1 = 0.f, n2 = 0.f, n3 = 0.f;
            if (h0 + 4 < H_) {
                const float* q = whp + (size_t)(h0 + 4) * S_;
                n0 = __ldg(q);
                n1 = __ldg(q + S_);
                n2 = __ldg(q + 2 * S_);
                n3 = __ldg(q + 3 * S_);
            }
#pragma unroll
            for (int i = 0; i < 4; i++) {
                float whv = (i == 0) ? p0 : (i == 1) ? p1 : (i == 2) ? p2 : p3;
                int h = h0 + i;
                float2 vw = sVW[h];
                float2 wp = sWp[h];
                float x0 = whv + wp.x;
                float x1 = whv + wp.y;
                if (PASS2) {
                    x0 = fmaf(c0, vw.y, x0);
                    x1 = fmaf(c1, vw.y, x1);
                }
                __half2 xh = __floats2half2_rn(x0, x1);
                unsigned th = tanh2(*(unsigned*)&xh);
                __half2 t2 = *(__half2*)&th;
                acc0 = fmaf(vw.x, __low2float(t2),  acc0);
                acc1 = fmaf(vw.x, __high2float(t2), acc1);
            }
            p0 = n0; p1 = n1; p2 = n2; p3 = n3;
        }

        float e0 = fminf(fmaxf(acc0, -30.0f), 30.0f);
        float e1 = fminf(fmaxf(acc1, -30.0f), 30.0f);
        // fixed max = 30 (clip upper bound) -> exp in [e^-60, 1], masked -> 0
        ex0 = mk ? 0.f : __expf(e0 - 30.0f);
        ex1 = mk ? 0.f : __expf(e1 - 30.0f);
    }

    // fused dual-sum reduction (2 syncs)
    int lane = tid & 31, wid = tid >> 5;  // 13 warps
    float s0 = ex0, s1 = ex1;
#pragma unroll
    for (int o = 16; o; o >>= 1) {
        s0 += __shfl_xor_sync(0xffffffffu, s0, o);
        s1 += __shfl_xor_sync(0xffffffffu, s1, o);
    }
    if (lane == 0) { sRed[wid] = s0; sRed[16 + wid] = s1; }
    __syncthreads();
    if (wid == 0) {
        float a0 = (lane < 13) ? sRed[lane]      : 0.f;
        float a1 = (lane < 13) ? sRed[16 + lane] : 0.f;
#pragma unroll
        for (int o = 16; o; o >>= 1) {
            a0 += __shfl_xor_sync(0xffffffffu, a0, o);
            a1 += __shfl_xor_sync(0xffffffffu, a1, o);
        }
        if (lane == 0) { sRed[32] = a0; sRed[33] = a1; }
    }
    __syncthreads();
    float inv0 = 1.0f / fmaxf(sRed[32], 1e-30f);
    float inv1 = 1.0f / fmaxf(sRed[33], 1e-30f);

    float lossAcc = 0.f;
    if (s < S_) {
        float a0 = ex0 * inv0;
        float a1 = ex1 * inv1;
        float* out0 = (PASS2 ? AoutParam : g_Apre);
        out0[row0 + s] = a0;
        out0[row1 + s] = a1;
        if (PASS2) lossAcc = fminf(a0, c0) + fminf(a1, c1);
    }

    if (PASS2) {
        __syncthreads();  // protect sRed reuse
#pragma unroll
        for (int o = 16; o; o >>= 1) lossAcc += __shfl_xor_sync(0xffffffffu, lossAcc, o);
        if (lane == 0) sRed[wid] = lossAcc;
        __syncthreads();
        if (tid == 0) {
            float p = 0.f;
#pragma unroll
            for (int i = 0; i < 13; i++) p += sRed[i];
            atomicAdd(loss, p * (1.0f / (B_ * T_)));
        }
    }
}

// ---------------------------------------------------------------------------
// cumsum: CTA = (b, 32 s-lanes); 128 threads = 32 s x 4 t-groups of 25.
// ---------------------------------------------------------------------------
__global__ __launch_bounds__(128) void cumsum_k(float* __restrict__ loss)
{
    constexpr int TSEG = 25;
    __shared__ float tot[4][32];

    if (blockIdx.x == 0 && blockIdx.y == 0 && threadIdx.x == 0) *loss = 0.f;

    int g  = threadIdx.x >> 5;
    int sl = threadIdx.x & 31;
    int s  = blockIdx.x * 32 + sl;
    int b  = blockIdx.y;
    bool act = (s < S_);

    size_t base = (size_t)b * T_ * S_ + s;
    float vals[TSEG];
    if (act) {
#pragma unroll
        for (int u = 0; u < TSEG; u++)
            vals[u] = g_Apre[base + (size_t)(g * TSEG + u) * S_];
    } else {
#pragma unroll
        for (int u = 0; u < TSEG; u++) vals[u] = 0.f;
    }

    float run = 0.f;
#pragma unroll
    for (int u = 0; u < TSEG; u++) {
        float x = vals[u];
        vals[u] = run;
        run += x;
    }
    tot[g][sl] = run;
    __syncthreads();

    float off = 0.f;
#pragma unroll
    for (int gg = 0; gg < 3; gg++)
        if (gg < g) off += tot[gg][sl];

    if (act) {
#pragma unroll
        for (int u = 0; u < TSEG; u++)
            g_cov[base + (size_t)(g * TSEG + u) * S_] = off + vals[u];
    }
}

// ---------------------------------------------------------------------------
extern "C" void kernel_launch(void* const* d_in, const int* in_sizes, int n_in,
                              void* d_out, int out_size)
{
    const float*         dec    = (const float*)d_in[0];
    const float*         enc    = (const float*)d_in[1];
    const unsigned char* mask   = (const unsigned char*)d_in[2];
    const float*         W_h    = (const float*)d_in[3];
    const float*         W_s    = (const float*)d_in[4];
    const float*         w_c    = (const float*)d_in[5];
    const float*         v      = (const float*)d_in[6];
    const float*         b_attn = (const float*)d_in[7];

    float* out  = (float*)d_out;
    float* ctx  = out;
    float* Afin = out + (size_t)B_ * T_ * H_;
    float* loss = Afin + (size_t)B_ * T_ * S_;

    // Fused projections: 50 WhT tiles + 13 Ws tiles -> grid (8, 63)
    dual_gemm<<<dim3(H_ / 32, 63), 256>>>(enc, W_h, dec, W_s, b_attn);

    // Pass 1: A_prelim
    attn_pass<false><<<B_ * (T_ / TGT), NTH>>>(mask, v, nullptr, nullptr, nullptr);

    // Shifted cumsum over t (also zeroes loss slot)
    cumsum_k<<<dim3((S_ + 31) / 32, B_), 128>>>(loss);

    // Pass 2: A_final + cov_loss
    attn_pass<true><<<B_ * (T_ / TGT), NTH>>>(mask, v, w_c, Afin, loss);

    // context[b] = A_final[b] @ enc[b]
    sgemm32<<<dim3(H_ / 32, (T_ + 31) / 32, B_), 256>>>(
        Afin, enc, ctx, T_, H_, S_,
        (long long)T_ * S_, (long long)S_ * H_, (long long)T_ * H_);
}

// round 12
// speedup vs baseline: 2.9269x; 1.0167x over previous
#include <cuda_runtime.h>
#include <cuda_fp16.h>

// Problem dims (fixed by reference setup_inputs)
constexpr int B_ = 8;
constexpr int T_ = 100;
constexpr int S_ = 400;
constexpr int H_ = 256;

constexpr int TGT = 2;    // t-rows per attn CTA
constexpr int NTH = 416;  // attn threads (13 warps; 400 active s-lanes)

// Scratch (device globals — no allocation allowed)
__device__ float g_WhT[B_ * H_ * S_];   // (enc @ W_h + b_attn)^T : [b][h][s]
__device__ float g_Ws [B_ * T_ * H_];   // dec @ W_s
__device__ float g_Apre[B_ * T_ * S_];  // A_prelim
__device__ float g_cov [B_ * T_ * S_];  // shifted cumsum of A_prelim

// Packed tanh: one MUFU evaluates tanh for both t-rows. Inputs/accum stay f32.
__device__ __forceinline__ unsigned tanh2(unsigned x) {
    unsigned y;
    asm("tanh.approx.f16x2 %0, %1;" : "=r"(y) : "r"(x));
    return y;
}

// ---------------------------------------------------------------------------
// Fused projection GEMMs, 64x32 tiles, 256 thr, 2x4 per thread.
// SMEM double-buffered: one __syncthreads per k-chunk, LDG issued early.
// blockIdx.y <  50 : WhT tile -> transposed store into g_WhT (+bias)
// blockIdx.y >= 50 : Ws  tile -> row-major store into g_Ws
// ---------------------------------------------------------------------------
__global__ __launch_bounds__(256) void dual_gemm(
    const float* __restrict__ enc, const float* __restrict__ W_h,
    const float* __restrict__ dec, const float* __restrict__ W_s,
    const float* __restrict__ bias)
{
    constexpr int K = H_, N = H_;
    bool isWh = blockIdx.y < 50;
    int  myTile = isWh ? blockIdx.y : (blockIdx.y - 50);
    int  M  = isWh ? B_ * S_ : B_ * T_;
    const float* A  = isWh ? enc : dec;
    const float* Bm = isWh ? W_h : W_s;

    int m0 = myTile * 64, n0 = blockIdx.x * 32;
    int tid = threadIdx.x;
    int tx = tid & 7;
    int ty = tid >> 3;

    __shared__ float As[2][16][68];
    __shared__ float Bs[2][16][36];
    __shared__ float Ts[32][65];

    float acc[2][4] = {};

    int lm  = tid >> 2;
    int lk4 = tid & 3;
    int bkr = tid >> 4;
    int bnc = tid & 15;

    // prologue: chunk 0 -> buffer 0
    {
        float4 av = make_float4(0.f, 0.f, 0.f, 0.f);
        int gm = m0 + lm;
        if (gm < M) av = *(const float4*)(A + (size_t)gm * K + lk4 * 4);
        As[0][lk4 * 4 + 0][lm] = av.x;
        As[0][lk4 * 4 + 1][lm] = av.y;
        As[0][lk4 * 4 + 2][lm] = av.z;
        As[0][lk4 * 4 + 3][lm] = av.w;
        float2 bv = *(const float2*)(Bm + (size_t)bkr * N + n0 + bnc * 2);
        Bs[0][bkr][bnc * 2 + 0] = bv.x;
        Bs[0][bkr][bnc * 2 + 1] = bv.y;
    }
    __syncthreads();

    int buf = 0;
    for (int k = 0; k < K; k += 16) {
        bool hasNext = (k + 16 < K);
        float4 av2 = make_float4(0.f, 0.f, 0.f, 0.f);
        float2 bv2 = make_float2(0.f, 0.f);
        if (hasNext) {
            int gm = m0 + lm;
            if (gm < M) av2 = *(const float4*)(A + (size_t)gm * K + k + 16 + lk4 * 4);
            bv2 = *(const float2*)(Bm + (size_t)(k + 16 + bkr) * N + n0 + bnc * 2);
        }
#pragma unroll
        for (int kk = 0; kk < 16; kk++) {
            float2 a = *(float2*)&As[buf][kk][ty * 2];
            float4 b = *(float4*)&Bs[buf][kk][tx * 4];
            acc[0][0] = fmaf(a.x, b.x, acc[0][0]);
            acc[0][1] = fmaf(a.x, b.y, acc[0][1]);
            acc[0][2] = fmaf(a.x, b.z, acc[0][2]);
            acc[0][3] = fmaf(a.x, b.w, acc[0][3]);
            acc[1][0] = fmaf(a.y, b.x, acc[1][0]);
            acc[1][1] = fmaf(a.y, b.y, acc[1][1]);
            acc[1][2] = fmaf(a.y, b.z, acc[1][2]);
            acc[1][3] = fmaf(a.y, b.w, acc[1][3]);
        }
        if (hasNext) {
            int nb = buf ^ 1;
            As[nb][lk4 * 4 + 0][lm] = av2.x;
            As[nb][lk4 * 4 + 1][lm] = av2.y;
            As[nb][lk4 * 4 + 2][lm] = av2.z;
            As[nb][lk4 * 4 + 3][lm] = av2.w;
            Bs[nb][bkr][bnc * 2 + 0] = bv2.x;
            Bs[nb][bkr][bnc * 2 + 1] = bv2.y;
            __syncthreads();
            buf = nb;
        }
    }

    if (isWh) {
        __syncthreads();  // Ts overlaps nothing, but protect vs in-flight reads
#pragma unroll
        for (int j = 0; j < 4; j++) {
            float bi = bias[n0 + tx * 4 + j];
#pragma unroll
            for (int i = 0; i < 2; i++)
                Ts[tx * 4 + j][ty * 2 + i] = acc[i][j] + bi;
        }
        __syncthreads();
#pragma unroll
        for (int kk = 0; kk < 8; kk++) {
            int e  = tid + 256 * kk;
            int h  = e >> 6;
            int sl = e & 63;
            int m  = m0 + sl;
            int b  = m / S_;
            int s  = m - b * S_;
            g_WhT[(size_t)b * H_ * S_ + (size_t)(n0 + h) * S_ + s] = Ts[h][sl];
        }
    } else {
#pragma unroll
        for (int i = 0; i < 2; i++) {
            int gm = m0 + ty * 2 + i;
            if (gm < M) {
#pragma unroll
                for (int j = 0; j < 4; j++)
                    g_Ws[(size_t)gm * N + n0 + tx * 4 + j] = acc[i][j];
            }
        }
    }
}

// ---------------------------------------------------------------------------
// Batched 64x32-tile SGEMM, 2x4 per thread, double-buffered (context GEMM).
// ---------------------------------------------------------------------------
__global__ __launch_bounds__(256) void gemm_ctx(
    const float* __restrict__ Ain, const float* __restrict__ Bin,
    float* __restrict__ Cout, int M, int N, int K,
    long long sA, long long sB, long long sC)
{
    const float* A  = Ain + (size_t)blockIdx.z * sA;
    const float* Bm = Bin + (size_t)blockIdx.z * sB;
    float*       C  = Cout + (size_t)blockIdx.z * sC;

    int m0 = blockIdx.y * 64, n0 = blockIdx.x * 32;
    int tid = threadIdx.x;
    int tx = tid & 7;
    int ty = tid >> 3;

    __shared__ float As[2][16][68];
    __shared__ float Bs[2][16][36];

    float acc[2][4] = {};

    int lm  = tid >> 2;
    int lk4 = tid & 3;
    int bkr = tid >> 4;
    int bnc = tid & 15;

    {
        float4 av = make_float4(0.f, 0.f, 0.f, 0.f);
        int gm = m0 + lm;
        if (gm < M) av = *(const float4*)(A + (size_t)gm * K + lk4 * 4);
        As[0][lk4 * 4 + 0][lm] = av.x;
        As[0][lk4 * 4 + 1][lm] = av.y;
        As[0][lk4 * 4 + 2][lm] = av.z;
        As[0][lk4 * 4 + 3][lm] = av.w;
        float2 bv = *(const float2*)(Bm + (size_t)bkr * N + n0 + bnc * 2);
        Bs[0][bkr][bnc * 2 + 0] = bv.x;
        Bs[0][bkr][bnc * 2 + 1] = bv.y;
    }
    __syncthreads();

    int buf = 0;
    for (int k = 0; k < K; k += 16) {
        bool hasNext = (k + 16 < K);
        float4 av2 = make_float4(0.f, 0.f, 0.f, 0.f);
        float2 bv2 = make_float2(0.f, 0.f);
        if (hasNext) {
            int gm = m0 + lm;
            if (gm < M) av2 = *(const float4*)(A + (size_t)gm * K + k + 16 + lk4 * 4);
            bv2 = *(const float2*)(Bm + (size_t)(k + 16 + bkr) * N + n0 + bnc * 2);
        }
#pragma unroll
        for (int kk = 0; kk < 16; kk++) {
            float2 a = *(float2*)&As[buf][kk][ty * 2];
            float4 b = *(float4*)&Bs[buf][kk][tx * 4];
            acc[0][0] = fmaf(a.x, b.x, acc[0][0]);
            acc[0][1] = fmaf(a.x, b.y, acc[0][1]);
            acc[0][2] = fmaf(a.x, b.z, acc[0][2]);
            acc[0][3] = fmaf(a.x, b.w, acc[0][3]);
            acc[1][0] = fmaf(a.y, b.x, acc[1][0]);
            acc[1][1] = fmaf(a.y, b.y, acc[1][1]);
            acc[1][2] = fmaf(a.y, b.z, acc[1][2]);
            acc[1][3] = fmaf(a.y, b.w, acc[1][3]);
        }
        if (hasNext) {
            int nb = buf ^ 1;
            As[nb][lk4 * 4 + 0][lm] = av2.x;
            As[nb][lk4 * 4 + 1][lm] = av2.y;
            As[nb][lk4 * 4 + 2][lm] = av2.z;
            As[nb][lk4 * 4 + 3][lm] = av2.w;
            Bs[nb][bkr][bnc * 2 + 0] = bv2.x;
            Bs[nb][bkr][bnc * 2 + 1] = bv2.y;
            __syncthreads();
            buf = nb;
        }
    }

#pragma unroll
    for (int i = 0; i < 2; i++) {
        int gm = m0 + ty * 2 + i;
        if (gm < M) {
#pragma unroll
            for (int j = 0; j < 4; j++)
                C[(size_t)gm * N + n0 + tx * 4 + j] = acc[i][j];
        }
    }
}

// ---------------------------------------------------------------------------
// attn_pass: R11 structure; branchless clamped prefetch (no BSSY/BSYNC in
// the mainloop — last iteration harmlessly reloads h=0..3).
// ---------------------------------------------------------------------------
template <bool PASS2>
__global__ __launch_bounds__(NTH, 3) void attn_pass(
    const unsigned char* __restrict__ mask,
    const float* __restrict__ v,
    const float* __restrict__ wc,
    float* __restrict__ AoutParam,
    float* __restrict__ loss)
{
    __shared__ float2 sVW[H_];        // (v[h], wc[h])
    __shared__ float2 sWp[H_];        // (ws_t0[h], ws_t1[h])
    __shared__ float  sRed[48];

    int tid = threadIdx.x;
    int b   = blockIdx.x / (T_ / TGT);
    int t0  = (blockIdx.x % (T_ / TGT)) * TGT;

    const float* ws0 = g_Ws + ((size_t)b * T_ + t0) * H_;
    for (int h = tid; h < H_; h += NTH) {
        sVW[h] = make_float2(v[h], PASS2 ? wc[h] : 0.f);
        sWp[h] = make_float2(ws0[h], ws0[H_ + h]);
    }
    __syncthreads();

    size_t row0 = ((size_t)b * T_ + t0) * S_;
    size_t row1 = row0 + S_;

    int s = tid;
    float ex0 = 0.f, ex1 = 0.f;
    float c0 = 0.f, c1 = 0.f;
    if (s < S_) {
        const float* whp = g_WhT + (size_t)b * H_ * S_ + s;
        bool mk = mask[b * S_ + s] != 0;
        if (PASS2) { c0 = g_cov[row0 + s]; c1 = g_cov[row1 + s]; }
        float acc0 = 0.f, acc1 = 0.f;

        // rotating scalar prefetch, depth 4; branchless tail (clamped index)
        float p0 = __ldg(whp);
        float p1 = __ldg(whp + S_);
        float p2 = __ldg(whp + 2 * S_);
        float p3 = __ldg(whp + 3 * S_);

#pragma unroll 2
        for (int h0 = 0; h0 < H_; h0 += 4) {
            int hn = (h0 + 4 < H_) ? (h0 + 4) : 0;   // SEL, no branch
            const float* q = whp + (size_t)hn * S_;
            float n0 = __ldg(q);
            float n1 = __ldg(q + S_);
            float n2 = __ldg(q + 2 * S_);
            float n3 = __ldg(q + 3 * S_);
#pragma unroll
            for (int i = 0; i < 4; i++) {
                float whv = (i == 0) ? p0 : (i == 1) ? p1 : (i == 2) ? p2 : p3;
                int h = h0 + i;
                float2 vw = sVW[h];
                float2 wp = sWp[h];
                float x0 = whv + wp.x;
                float x1 = whv + wp.y;
                if (PASS2) {
                    x0 = fmaf(c0, vw.y, x0);
                    x1 = fmaf(c1, vw.y, x1);
                }
                __half2 xh = __floats2half2_rn(x0, x1);
                unsigned th = tanh2(*(unsigned*)&xh);
                __half2 t2 = *(__half2*)&th;
                acc0 = fmaf(vw.x, __low2float(t2),  acc0);
                acc1 = fmaf(vw.x, __high2float(t2), acc1);
            }
            p0 = n0; p1 = n1; p2 = n2; p3 = n3;
        }

        float e0 = fminf(fmaxf(acc0, -30.0f), 30.0f);
        float e1 = fminf(fmaxf(acc1, -30.0f), 30.0f);
        // fixed max = 30 (clip upper bound) -> exp in [e^-60, 1], masked -> 0
        ex0 = mk ? 0.f : __expf(e0 - 30.0f);
        ex1 = mk ? 0.f : __expf(e1 - 30.0f);
    }

    // fused dual-sum reduction (2 syncs)
    int lane = tid & 31, wid = tid >> 5;  // 13 warps
    float s0 = ex0, s1 = ex1;
#pragma unroll
    for (int o = 16; o; o >>= 1) {
        s0 += __shfl_xor_sync(0xffffffffu, s0, o);
        s1 += __shfl_xor_sync(0xffffffffu, s1, o);
    }
    if (lane == 0) { sRed[wid] = s0; sRed[16 + wid] = s1; }
    __syncthreads();
    if (wid == 0) {
        float a0 = (lane < 13) ? sRed[lane]      : 0.f;
        float a1 = (lane < 13) ? sRed[16 + lane] : 0.f;
#pragma unroll
        for (int o = 16; o; o >>= 1) {
            a0 += __shfl_xor_sync(0xffffffffu, a0, o);
            a1 += __shfl_xor_sync(0xffffffffu, a1, o);
        }
        if (lane == 0) { sRed[32] = a0; sRed[33] = a1; }
    }
    __syncthreads();
    float inv0 = 1.0f / fmaxf(sRed[32], 1e-30f);
    float inv1 = 1.0f / fmaxf(sRed[33], 1e-30f);

    float lossAcc = 0.f;
    if (s < S_) {
        float a0 = ex0 * inv0;
        float a1 = ex1 * inv1;
        float* out0 = (PASS2 ? AoutParam : g_Apre);
        out0[row0 + s] = a0;
        out0[row1 + s] = a1;
        if (PASS2) lossAcc = fminf(a0, c0) + fminf(a1, c1);
    }

    if (PASS2) {
        __syncthreads();  // protect sRed reuse
#pragma unroll
        for (int o = 16; o; o >>= 1) lossAcc += __shfl_xor_sync(0xffffffffu, lossAcc, o);
        if (lane == 0) sRed[wid] = lossAcc;
        __syncthreads();
        if (tid == 0) {
            float p = 0.f;
#pragma unroll
            for (int i = 0; i < 13; i++) p += sRed[i];
            atomicAdd(loss, p * (1.0f / (B_ * T_)));
        }
    }
}

// ---------------------------------------------------------------------------
// cumsum: CTA = (b, 32 s-lanes); 128 threads = 32 s x 4 t-groups of 25.
// ---------------------------------------------------------------------------
__global__ __launch_bounds__(128) void cumsum_k(float* __restrict__ loss)
{
    constexpr int TSEG = 25;
    __shared__ float tot[4][32];

    if (blockIdx.x == 0 && blockIdx.y == 0 && threadIdx.x == 0) *loss = 0.f;

    int g  = threadIdx.x >> 5;
    int sl = threadIdx.x & 31;
    int s  = blockIdx.x * 32 + sl;
    int b  = blockIdx.y;
    bool act = (s < S_);

    size_t base = (size_t)b * T_ * S_ + s;
    float vals[TSEG];
    if (act) {
#pragma unroll
        for (int u = 0; u < TSEG; u++)
            vals[u] = g_Apre[base + (size_t)(g * TSEG + u) * S_];
    } else {
#pragma unroll
        for (int u = 0; u < TSEG; u++) vals[u] = 0.f;
    }

    float run = 0.f;
#pragma unroll
    for (int u = 0; u < TSEG; u++) {
        float x = vals[u];
        vals[u] = run;
        run += x;
    }
    tot[g][sl] = run;
    __syncthreads();

    float off = 0.f;
#pragma unroll
    for (int gg = 0; gg < 3; gg++)
        if (gg < g) off += tot[gg][sl];

    if (act) {
#pragma unroll
        for (int u = 0; u < TSEG; u++)
            g_cov[base + (size_t)(g * TSEG + u) * S_] = off + vals[u];
    }
}

// ---------------------------------------------------------------------------
extern "C" void kernel_launch(void* const* d_in, const int* in_sizes, int n_in,
                              void* d_out, int out_size)
{
    const float*         dec    = (const float*)d_in[0];
    const float*         enc    = (const float*)d_in[1];
    const unsigned char* mask   = (const unsigned char*)d_in[2];
    const float*         W_h    = (const float*)d_in[3];
    const float*         W_s    = (const float*)d_in[4];
    const float*         w_c    = (const float*)d_in[5];
    const float*         v      = (const float*)d_in[6];
    const float*         b_attn = (const float*)d_in[7];

    float* out  = (float*)d_out;
    float* ctx  = out;
    float* Afin = out + (size_t)B_ * T_ * H_;
    float* loss = Afin + (size_t)B_ * T_ * S_;

    // Fused projections: 50 WhT tiles + 13 Ws tiles -> grid (8, 63)
    dual_gemm<<<dim3(H_ / 32, 63), 256>>>(enc, W_h, dec, W_s, b_attn);

    // Pass 1: A_prelim
    attn_pass<false><<<B_ * (T_ / TGT), NTH>>>(mask, v, nullptr, nullptr, nullptr);

    // Shifted cumsum over t (also zeroes loss slot)
    cumsum_k<<<dim3((S_ + 31) / 32, B_), 128>>>(loss);

    // Pass 2: A_final + cov_loss
    attn_pass<true><<<B_ * (T_ / TGT), NTH>>>(mask, v, w_c, Afin, loss);

    // context[b] = A_final[b] @ enc[b]  (M=100, N=256, K=400, batched)
    gemm_ctx<<<dim3(H_ / 32, (T_ + 63) / 64, B_), 256>>>(
        Afin, enc, ctx, T_, H_, S_,
        (long long)T_ * S_, (long long)S_ * H_, (long long)T_ * H_);
}

// round 13
// speedup vs baseline: 2.9876x; 1.0207x over previous
#include <cuda_runtime.h>
#include <cuda_fp16.h>

// Problem dims (fixed by reference setup_inputs)
constexpr int B_ = 8;
constexpr int T_ = 100;
constexpr int S_ = 400;
constexpr int H_ = 256;

constexpr int TGT = 2;    // t-rows per attn CTA
constexpr int NTH = 416;  // attn threads (13 warps; 400 active s-lanes)

// Scratch (device globals — no allocation allowed)
__device__ float g_WhT[B_ * H_ * S_];   // (enc @ W_h + b_attn)^T : [b][h][s]
__device__ float g_Ws [B_ * T_ * H_];   // dec @ W_s
__device__ float g_Apre[B_ * T_ * S_];  // A_prelim

// Packed tanh: one MUFU evaluates tanh for both t-rows. Inputs/accum stay f32.
__device__ __forceinline__ unsigned tanh2(unsigned x) {
    unsigned y;
    asm("tanh.approx.f16x2 %0, %1;" : "=r"(y) : "r"(x));
    return y;
}

// ---------------------------------------------------------------------------
// Fused projection GEMMs, 64x32 tiles, 256 thr, 2x4 per thread.
// SMEM double-buffered: one __syncthreads per k-chunk, LDG issued early.
// blockIdx.y <  50 : WhT tile -> transposed store into g_WhT (+bias)
// blockIdx.y >= 50 : Ws  tile -> row-major store into g_Ws
// ---------------------------------------------------------------------------
__global__ __launch_bounds__(256) void dual_gemm(
    const float* __restrict__ enc, const float* __restrict__ W_h,
    const float* __restrict__ dec, const float* __restrict__ W_s,
    const float* __restrict__ bias)
{
    constexpr int K = H_, N = H_;
    bool isWh = blockIdx.y < 50;
    int  myTile = isWh ? blockIdx.y : (blockIdx.y - 50);
    int  M  = isWh ? B_ * S_ : B_ * T_;
    const float* A  = isWh ? enc : dec;
    const float* Bm = isWh ? W_h : W_s;

    int m0 = myTile * 64, n0 = blockIdx.x * 32;
    int tid = threadIdx.x;
    int tx = tid & 7;
    int ty = tid >> 3;

    __shared__ float As[2][16][68];
    __shared__ float Bs[2][16][36];
    __shared__ float Ts[32][65];

    float acc[2][4] = {};

    int lm  = tid >> 2;
    int lk4 = tid & 3;
    int bkr = tid >> 4;
    int bnc = tid & 15;

    // prologue: chunk 0 -> buffer 0
    {
        float4 av = make_float4(0.f, 0.f, 0.f, 0.f);
        int gm = m0 + lm;
        if (gm < M) av = *(const float4*)(A + (size_t)gm * K + lk4 * 4);
        As[0][lk4 * 4 + 0][lm] = av.x;
        As[0][lk4 * 4 + 1][lm] = av.y;
        As[0][lk4 * 4 + 2][lm] = av.z;
        As[0][lk4 * 4 + 3][lm] = av.w;
        float2 bv = *(const float2*)(Bm + (size_t)bkr * N + n0 + bnc * 2);
        Bs[0][bkr][bnc * 2 + 0] = bv.x;
        Bs[0][bkr][bnc * 2 + 1] = bv.y;
    }
    __syncthreads();

    int buf = 0;
    for (int k = 0; k < K; k += 16) {
        bool hasNext = (k + 16 < K);
        float4 av2 = make_float4(0.f, 0.f, 0.f, 0.f);
        float2 bv2 = make_float2(0.f, 0.f);
        if (hasNext) {
            int gm = m0 + lm;
            if (gm < M) av2 = *(const float4*)(A + (size_t)gm * K + k + 16 + lk4 * 4);
            bv2 = *(const float2*)(Bm + (size_t)(k + 16 + bkr) * N + n0 + bnc * 2);
        }
#pragma unroll
        for (int kk = 0; kk < 16; kk++) {
            float2 a = *(float2*)&As[buf][kk][ty * 2];
            float4 b = *(float4*)&Bs[buf][kk][tx * 4];
            acc[0][0] = fmaf(a.x, b.x, acc[0][0]);
            acc[0][1] = fmaf(a.x, b.y, acc[0][1]);
            acc[0][2] = fmaf(a.x, b.z, acc[0][2]);
            acc[0][3] = fmaf(a.x, b.w, acc[0][3]);
            acc[1][0] = fmaf(a.y, b.x, acc[1][0]);
            acc[1][1] = fmaf(a.y, b.y, acc[1][1]);
            acc[1][2] = fmaf(a.y, b.z, acc[1][2]);
            acc[1][3] = fmaf(a.y, b.w, acc[1][3]);
        }
        if (hasNext) {
            int nb = buf ^ 1;
            As[nb][lk4 * 4 + 0][lm] = av2.x;
            As[nb][lk4 * 4 + 1][lm] = av2.y;
            As[nb][lk4 * 4 + 2][lm] = av2.z;
            As[nb][lk4 * 4 + 3][lm] = av2.w;
            Bs[nb][bkr][bnc * 2 + 0] = bv2.x;
            Bs[nb][bkr][bnc * 2 + 1] = bv2.y;
            __syncthreads();
            buf = nb;
        }
    }

    if (isWh) {
        __syncthreads();  // protect Ts vs in-flight As/Bs reads
#pragma unroll
        for (int j = 0; j < 4; j++) {
            float bi = bias[n0 + tx * 4 + j];
#pragma unroll
            for (int i = 0; i < 2; i++)
                Ts[tx * 4 + j][ty * 2 + i] = acc[i][j] + bi;
        }
        __syncthreads();
#pragma unroll
        for (int kk = 0; kk < 8; kk++) {
            int e  = tid + 256 * kk;
            int h  = e >> 6;
            int sl = e & 63;
            int m  = m0 + sl;
            int b  = m / S_;
            int s  = m - b * S_;
            g_WhT[(size_t)b * H_ * S_ + (size_t)(n0 + h) * S_ + s] = Ts[h][sl];
        }
    } else {
#pragma unroll
        for (int i = 0; i < 2; i++) {
            int gm = m0 + ty * 2 + i;
            if (gm < M) {
#pragma unroll
                for (int j = 0; j < 4; j++)
                    g_Ws[(size_t)gm * N + n0 + tx * 4 + j] = acc[i][j];
            }
        }
    }
}

// ---------------------------------------------------------------------------
// Batched 64x32-tile SGEMM, 2x4 per thread, double-buffered (context GEMM).
// ---------------------------------------------------------------------------
__global__ __launch_bounds__(256) void gemm_ctx(
    const float* __restrict__ Ain, const float* __restrict__ Bin,
    float* __restrict__ Cout, int M, int N, int K,
    long long sA, long long sB, long long sC)
{
    const float* A  = Ain + (size_t)blockIdx.z * sA;
    const float* Bm = Bin + (size_t)blockIdx.z * sB;
    float*       C  = Cout + (size_t)blockIdx.z * sC;

    int m0 = blockIdx.y * 64, n0 = blockIdx.x * 32;
    int tid = threadIdx.x;
    int tx = tid & 7;
    int ty = tid >> 3;

    __shared__ float As[2][16][68];
    __shared__ float Bs[2][16][36];

    float acc[2][4] = {};

    int lm  = tid >> 2;
    int lk4 = tid & 3;
    int bkr = tid >> 4;
    int bnc = tid & 15;

    {
        float4 av = make_float4(0.f, 0.f, 0.f, 0.f);
        int gm = m0 + lm;
        if (gm < M) av = *(const float4*)(A + (size_t)gm * K + lk4 * 4);
        As[0][lk4 * 4 + 0][lm] = av.x;
        As[0][lk4 * 4 + 1][lm] = av.y;
        As[0][lk4 * 4 + 2][lm] = av.z;
        As[0][lk4 * 4 + 3][lm] = av.w;
        float2 bv = *(const float2*)(Bm + (size_t)bkr * N + n0 + bnc * 2);
        Bs[0][bkr][bnc * 2 + 0] = bv.x;
        Bs[0][bkr][bnc * 2 + 1] = bv.y;
    }
    __syncthreads();

    int buf = 0;
    for (int k = 0; k < K; k += 16) {
        bool hasNext = (k + 16 < K);
        float4 av2 = make_float4(0.f, 0.f, 0.f, 0.f);
        float2 bv2 = make_float2(0.f, 0.f);
        if (hasNext) {
            int gm = m0 + lm;
            if (gm < M) av2 = *(const float4*)(A + (size_t)gm * K + k + 16 + lk4 * 4);
            bv2 = *(const float2*)(Bm + (size_t)(k + 16 + bkr) * N + n0 + bnc * 2);
        }
#pragma unroll
        for (int kk = 0; kk < 16; kk++) {
            float2 a = *(float2*)&As[buf][kk][ty * 2];
            float4 b = *(float4*)&Bs[buf][kk][tx * 4];
            acc[0][0] = fmaf(a.x, b.x, acc[0][0]);
            acc[0][1] = fmaf(a.x, b.y, acc[0][1]);
            acc[0][2] = fmaf(a.x, b.z, acc[0][2]);
            acc[0][3] = fmaf(a.x, b.w, acc[0][3]);
            acc[1][0] = fmaf(a.y, b.x, acc[1][0]);
            acc[1][1] = fmaf(a.y, b.y, acc[1][1]);
            acc[1][2] = fmaf(a.y, b.z, acc[1][2]);
            acc[1][3] = fmaf(a.y, b.w, acc[1][3]);
        }
        if (hasNext) {
            int nb = buf ^ 1;
            As[nb][lk4 * 4 + 0][lm] = av2.x;
            As[nb][lk4 * 4 + 1][lm] = av2.y;
            As[nb][lk4 * 4 + 2][lm] = av2.z;
            As[nb][lk4 * 4 + 3][lm] = av2.w;
            Bs[nb][bkr][bnc * 2 + 0] = bv2.x;
            Bs[nb][bkr][bnc * 2 + 1] = bv2.y;
            __syncthreads();
            buf = nb;
        }
    }

#pragma unroll
    for (int i = 0; i < 2; i++) {
        int gm = m0 + ty * 2 + i;
        if (gm < M) {
#pragma unroll
            for (int j = 0; j < 4; j++)
                C[(size_t)gm * N + n0 + tx * 4 + j] = acc[i][j];
        }
    }
}

// ---------------------------------------------------------------------------
// attn_pass: R12 structure + fused coverage cumsum in the PASS2 prologue
// (thread s sums Apre[b, 0..t0, s] directly -> c0/c1 in regs; no g_cov,
// no cumsum kernel). Pass1 zeroes the loss slot.
// ---------------------------------------------------------------------------
template <bool PASS2>
__global__ __launch_bounds__(NTH, 3) void attn_pass(
    const unsigned char* __restrict__ mask,
    const float* __restrict__ v,
    const float* __restrict__ wc,
    float* __restrict__ AoutParam,
    float* __restrict__ loss)
{
    __shared__ float2 sVW[H_];        // (v[h], wc[h])
    __shared__ float2 sWp[H_];        // (ws_t0[h], ws_t1[h])
    __shared__ float  sRed[48];

    int tid = threadIdx.x;
    int b   = blockIdx.x / (T_ / TGT);
    int t0  = (blockIdx.x % (T_ / TGT)) * TGT;

    if (!PASS2 && blockIdx.x == 0 && tid == 0) *loss = 0.f;

    const float* ws0 = g_Ws + ((size_t)b * T_ + t0) * H_;
    for (int h = tid; h < H_; h += NTH) {
        sVW[h] = make_float2(v[h], PASS2 ? wc[h] : 0.f);
        sWp[h] = make_float2(ws0[h], ws0[H_ + h]);
    }
    __syncthreads();

    size_t row0 = ((size_t)b * T_ + t0) * S_;
    size_t row1 = row0 + S_;

    int s = tid;
    float ex0 = 0.f, ex1 = 0.f;
    float c0 = 0.f, c1 = 0.f;
    if (s < S_) {
        const float* whp = g_WhT + (size_t)b * H_ * S_ + s;
        bool mk = mask[b * S_ + s] != 0;

        if (PASS2) {
            // fused shifted cumsum: c0 = sum_{t'<t0} Apre, c1 = c0 + Apre[t0]
            const float* ap = g_Apre + (size_t)b * T_ * S_ + s;
            float sum = 0.f;
            int t = 0;
            for (; t + 4 <= t0; t += 4) {
                float a0 = __ldg(ap + (size_t)t * S_);
                float a1 = __ldg(ap + (size_t)(t + 1) * S_);
                float a2 = __ldg(ap + (size_t)(t + 2) * S_);
                float a3 = __ldg(ap + (size_t)(t + 3) * S_);
                sum += (a0 + a1) + (a2 + a3);
            }
            for (; t < t0; t++) sum += __ldg(ap + (size_t)t * S_);
            c0 = sum;
            c1 = sum + __ldg(ap + (size_t)t0 * S_);
        }

        float acc0 = 0.f, acc1 = 0.f;

        // rotating scalar prefetch, depth 4; branchless tail (clamped index)
        float p0 = __ldg(whp);
        float p1 = __ldg(whp + S_);
        float p2 = __ldg(whp + 2 * S_);
        float p3 = __ldg(whp + 3 * S_);

#pragma unroll 2
        for (int h0 = 0; h0 < H_; h0 += 4) {
            int hn = (h0 + 4 < H_) ? (h0 + 4) : 0;   // SEL, no branch
            const float* q = whp + (size_t)hn * S_;
            float n0 = __ldg(q);
            float n1 = __ldg(q + S_);
            float n2 = __ldg(q + 2 * S_);
            float n3 = __ldg(q + 3 * S_);
#pragma unroll
            for (int i = 0; i < 4; i++) {
                float whv = (i == 0) ? p0 : (i == 1) ? p1 : (i == 2) ? p2 : p3;
                int h = h0 + i;
                float2 vw = sVW[h];
                float2 wp = sWp[h];
                float x0 = whv + wp.x;
                float x1 = whv + wp.y;
                if (PASS2) {
                    x0 = fmaf(c0, vw.y, x0);
                    x1 = fmaf(c1, vw.y, x1);
                }
                __half2 xh = __floats2half2_rn(x0, x1);
                unsigned th = tanh2(*(unsigned*)&xh);
                __half2 t2 = *(__half2*)&th;
                acc0 = fmaf(vw.x, __low2float(t2),  acc0);
                acc1 = fmaf(vw.x, __high2float(t2), acc1);
            }
            p0 = n0; p1 = n1; p2 = n2; p3 = n3;
        }

        float e0 = fminf(fmaxf(acc0, -30.0f), 30.0f);
        float e1 = fminf(fmaxf(acc1, -30.0f), 30.0f);
        // fixed max = 30 (clip upper bound) -> exp in [e^-60, 1], masked -> 0
        ex0 = mk ? 0.f : __expf(e0 - 30.0f);
        ex1 = mk ? 0.f : __expf(e1 - 30.0f);
    }

    // fused dual-sum reduction (2 syncs)
    int lane = tid & 31, wid = tid >> 5;  // 13 warps
    float s0 = ex0, s1 = ex1;
#pragma unroll
    for (int o = 16; o; o >>= 1) {
        s0 += __shfl_xor_sync(0xffffffffu, s0, o);
        s1 += __shfl_xor_sync(0xffffffffu, s1, o);
    }
    if (lane == 0) { sRed[wid] = s0; sRed[16 + wid] = s1; }
    __syncthreads();
    if (wid == 0) {
        float a0 = (lane < 13) ? sRed[lane]      : 0.f;
        float a1 = (lane < 13) ? sRed[16 + lane] : 0.f;
#pragma unroll
        for (int o = 16; o; o >>= 1) {
            a0 += __shfl_xor_sync(0xffffffffu, a0, o);
            a1 += __shfl_xor_sync(0xffffffffu, a1, o);
        }
        if (lane == 0) { sRed[32] = a0; sRed[33] = a1; }
    }
    __syncthreads();
    float inv0 = 1.0f / fmaxf(sRed[32], 1e-30f);
    float inv1 = 1.0f / fmaxf(sRed[33], 1e-30f);

    float lossAcc = 0.f;
    if (s < S_) {
        float a0 = ex0 * inv0;
        float a1 = ex1 * inv1;
        float* out0 = (PASS2 ? AoutParam : g_Apre);
        out0[row0 + s] = a0;
        out0[row1 + s] = a1;
        if (PASS2) lossAcc = fminf(a0, c0) + fminf(a1, c1);
    }

    if (PASS2) {
        __syncthreads();  // protect sRed reuse
#pragma unroll
        for (int o = 16; o; o >>= 1) lossAcc += __shfl_xor_sync(0xffffffffu, lossAcc, o);
        if (lane == 0) sRed[wid] = lossAcc;
        __syncthreads();
        if (tid == 0) {
            float p = 0.f;
#pragma unroll
            for (int i = 0; i < 13; i++) p += sRed[i];
            atomicAdd(loss, p * (1.0f / (B_ * T_)));
        }
    }
}

// ---------------------------------------------------------------------------
extern "C" void kernel_launch(void* const* d_in, const int* in_sizes, int n_in,
                              void* d_out, int out_size)
{
    const float*         dec    = (const float*)d_in[0];
    const float*         enc    = (const float*)d_in[1];
    const unsigned char* mask   = (const unsigned char*)d_in[2];
    const float*         W_h    = (const float*)d_in[3];
    const float*         W_s    = (const float*)d_in[4];
    const float*         w_c    = (const float*)d_in[5];
    const float*         v      = (const float*)d_in[6];
    const float*         b_attn = (const float*)d_in[7];

    float* out  = (float*)d_out;
    float* ctx  = out;
    float* Afin = out + (size_t)B_ * T_ * H_;
    float* loss = Afin + (size_t)B_ * T_ * S_;

    // Fused projections: 50 WhT tiles + 13 Ws tiles -> grid (8, 63)
    dual_gemm<<<dim3(H_ / 32, 63), 256>>>(enc, W_h, dec, W_s, b_attn);

    // Pass 1: A_prelim (also zeroes the loss slot)
    attn_pass<false><<<B_ * (T_ / TGT), NTH>>>(mask, v, nullptr, nullptr, loss);

    // Pass 2: A_final + cov_loss (cumsum fused into prologue)
    attn_pass<true><<<B_ * (T_ / TGT), NTH>>>(mask, v, w_c, Afin, loss);

    // context[b] = A_final[b] @ enc[b]  (M=100, N=256, K=400, batched)
    gemm_ctx<<<dim3(H_ / 32, (T_ + 63) / 64, B_), 256>>>(
        Afin, enc, ctx, T_, H_, S_,
        (long long)T_ * S_, (long long)S_ * H_, (long long)T_ * H_);
}

// round 14
// speedup vs baseline: 3.1226x; 1.0452x over previous
#include <cuda_runtime.h>
#include <cuda_fp16.h>

// Problem dims (fixed by reference setup_inputs)
constexpr int B_ = 8;
constexpr int T_ = 100;
constexpr int S_ = 400;
constexpr int H_ = 256;

constexpr int TGT = 2;    // t-rows per attn CTA
constexpr int NTH = 416;  // attn threads (13 warps; 400 active s-lanes)

// Scratch (device globals — no allocation allowed)
__device__ float g_WhT[B_ * H_ * S_];   // (enc @ W_h + b_attn)^T : [b][h][s]
__device__ float g_Ws [B_ * T_ * H_];   // dec @ W_s
__device__ float g_Apre[B_ * T_ * S_];  // A_prelim

// Packed tanh: one MUFU evaluates tanh for both t-rows. Inputs/accum stay f32.
__device__ __forceinline__ unsigned tanh2(unsigned x) {
    unsigned y;
    asm("tanh.approx.f16x2 %0, %1;" : "=r"(y) : "r"(x));
    return y;
}

// ---------------------------------------------------------------------------
// Fused projection GEMMs, 64x32 tiles, 256 thr, 2x4 per thread.
// SMEM double-buffered: one __syncthreads per k-chunk, LDG issued early.
// blockIdx.y <  50 : WhT tile -> transposed store into g_WhT (+bias)
// blockIdx.y >= 50 : Ws  tile -> row-major store into g_Ws
// ---------------------------------------------------------------------------
__global__ __launch_bounds__(256) void dual_gemm(
    const float* __restrict__ enc, const float* __restrict__ W_h,
    const float* __restrict__ dec, const float* __restrict__ W_s,
    const float* __restrict__ bias)
{
    constexpr int K = H_, N = H_;
    bool isWh = blockIdx.y < 50;
    int  myTile = isWh ? blockIdx.y : (blockIdx.y - 50);
    int  M  = isWh ? B_ * S_ : B_ * T_;
    const float* A  = isWh ? enc : dec;
    const float* Bm = isWh ? W_h : W_s;

    int m0 = myTile * 64, n0 = blockIdx.x * 32;
    int tid = threadIdx.x;
    int tx = tid & 7;
    int ty = tid >> 3;

    __shared__ float As[2][16][68];
    __shared__ float Bs[2][16][36];
    __shared__ float Ts[32][65];

    float acc[2][4] = {};

    int lm  = tid >> 2;
    int lk4 = tid & 3;
    int bkr = tid >> 4;
    int bnc = tid & 15;

    // prologue: chunk 0 -> buffer 0
    {
        float4 av = make_float4(0.f, 0.f, 0.f, 0.f);
        int gm = m0 + lm;
        if (gm < M) av = *(const float4*)(A + (size_t)gm * K + lk4 * 4);
        As[0][lk4 * 4 + 0][lm] = av.x;
        As[0][lk4 * 4 + 1][lm] = av.y;
        As[0][lk4 * 4 + 2][lm] = av.z;
        As[0][lk4 * 4 + 3][lm] = av.w;
        float2 bv = *(const float2*)(Bm + (size_t)bkr * N + n0 + bnc * 2);
        Bs[0][bkr][bnc * 2 + 0] = bv.x;
        Bs[0][bkr][bnc * 2 + 1] = bv.y;
    }
    __syncthreads();

    int buf = 0;
    for (int k = 0; k < K; k += 16) {
        bool hasNext = (k + 16 < K);
        float4 av2 = make_float4(0.f, 0.f, 0.f, 0.f);
        float2 bv2 = make_float2(0.f, 0.f);
        if (hasNext) {
            int gm = m0 + lm;
            if (gm < M) av2 = *(const float4*)(A + (size_t)gm * K + k + 16 + lk4 * 4);
            bv2 = *(const float2*)(Bm + (size_t)(k + 16 + bkr) * N + n0 + bnc * 2);
        }
#pragma unroll
        for (int kk = 0; kk < 16; kk++) {
            float2 a = *(float2*)&As[buf][kk][ty * 2];
            float4 b = *(float4*)&Bs[buf][kk][tx * 4];
            acc[0][0] = fmaf(a.x, b.x, acc[0][0]);
            acc[0][1] = fmaf(a.x, b.y, acc[0][1]);
            acc[0][2] = fmaf(a.x, b.z, acc[0][2]);
            acc[0][3] = fmaf(a.x, b.w, acc[0][3]);
            acc[1][0] = fmaf(a.y, b.x, acc[1][0]);
            acc[1][1] = fmaf(a.y, b.y, acc[1][1]);
            acc[1][2] = fmaf(a.y, b.z, acc[1][2]);
            acc[1][3] = fmaf(a.y, b.w, acc[1][3]);
        }
        if (hasNext) {
            int nb = buf ^ 1;
            As[nb][lk4 * 4 + 0][lm] = av2.x;
            As[nb][lk4 * 4 + 1][lm] = av2.y;
            As[nb][lk4 * 4 + 2][lm] = av2.z;
            As[nb][lk4 * 4 + 3][lm] = av2.w;
            Bs[nb][bkr][bnc * 2 + 0] = bv2.x;
            Bs[nb][bkr][bnc * 2 + 1] = bv2.y;
            __syncthreads();
            buf = nb;
        }
    }

    if (isWh) {
        __syncthreads();  // protect Ts vs in-flight As/Bs reads
#pragma unroll
        for (int j = 0; j < 4; j++) {
            float bi = bias[n0 + tx * 4 + j];
#pragma unroll
            for (int i = 0; i < 2; i++)
                Ts[tx * 4 + j][ty * 2 + i] = acc[i][j] + bi;
        }
        __syncthreads();
#pragma unroll
        for (int kk = 0; kk < 8; kk++) {
            int e  = tid + 256 * kk;
            int h  = e >> 6;
            int sl = e & 63;
            int m  = m0 + sl;
            int b  = m / S_;
            int s  = m - b * S_;
            g_WhT[(size_t)b * H_ * S_ + (size_t)(n0 + h) * S_ + s] = Ts[h][sl];
        }
    } else {
#pragma unroll
        for (int i = 0; i < 2; i++) {
            int gm = m0 + ty * 2 + i;
            if (gm < M) {
#pragma unroll
                for (int j = 0; j < 4; j++)
                    g_Ws[(size_t)gm * N + n0 + tx * 4 + j] = acc[i][j];
            }
        }
    }
}

// ---------------------------------------------------------------------------
// Context GEMM, split-K(2): blockIdx.z = b*2 + ksplit. 64x32 tiles,
// 2x4 per thread, double-buffered; partials combined via atomicAdd
// (ctx is zeroed by attn_pass<false>).
// ---------------------------------------------------------------------------
__global__ __launch_bounds__(256) void gemm_ctx(
    const float* __restrict__ Ain, const float* __restrict__ Bin,
    float* __restrict__ Cout, int M, int N, int Kfull,
    long long sA, long long sB, long long sC)
{
    int bz = blockIdx.z >> 1;
    int ks = blockIdx.z & 1;
    int kOff = ks ? 208 : 0;            // 13 chunks / 12 chunks
    int kLen = ks ? (Kfull - 208) : 208;

    const float* A  = Ain + (size_t)bz * sA + kOff;
    const float* Bm = Bin + (size_t)bz * sB + (size_t)kOff * N;
    float*       C  = Cout + (size_t)bz * sC;

    int m0 = blockIdx.y * 64, n0 = blockIdx.x * 32;
    int tid = threadIdx.x;
    int tx = tid & 7;
    int ty = tid >> 3;

    __shared__ float As[2][16][68];
    __shared__ float Bs[2][16][36];

    float acc[2][4] = {};

    int lm  = tid >> 2;
    int lk4 = tid & 3;
    int bkr = tid >> 4;
    int bnc = tid & 15;

    {
        float4 av = make_float4(0.f, 0.f, 0.f, 0.f);
        int gm = m0 + lm;
        if (gm < M) av = *(const float4*)(A + (size_t)gm * Kfull + lk4 * 4);
        As[0][lk4 * 4 + 0][lm] = av.x;
        As[0][lk4 * 4 + 1][lm] = av.y;
        As[0][lk4 * 4 + 2][lm] = av.z;
        As[0][lk4 * 4 + 3][lm] = av.w;
        float2 bv = *(const float2*)(Bm + (size_t)bkr * N + n0 + bnc * 2);
        Bs[0][bkr][bnc * 2 + 0] = bv.x;
        Bs[0][bkr][bnc * 2 + 1] = bv.y;
    }
    __syncthreads();

    int buf = 0;
    for (int k = 0; k < kLen; k += 16) {
        bool hasNext = (k + 16 < kLen);
        float4 av2 = make_float4(0.f, 0.f, 0.f, 0.f);
        float2 bv2 = make_float2(0.f, 0.f);
        if (hasNext) {
            int gm = m0 + lm;
            if (gm < M) av2 = *(const float4*)(A + (size_t)gm * Kfull + k + 16 + lk4 * 4);
            bv2 = *(const float2*)(Bm + (size_t)(k + 16 + bkr) * N + n0 + bnc * 2);
        }
#pragma unroll
        for (int kk = 0; kk < 16; kk++) {
            float2 a = *(float2*)&As[buf][kk][ty * 2];
            float4 b = *(float4*)&Bs[buf][kk][tx * 4];
            acc[0][0] = fmaf(a.x, b.x, acc[0][0]);
            acc[0][1] = fmaf(a.x, b.y, acc[0][1]);
            acc[0][2] = fmaf(a.x, b.z, acc[0][2]);
            acc[0][3] = fmaf(a.x, b.w, acc[0][3]);
            acc[1][0] = fmaf(a.y, b.x, acc[1][0]);
            acc[1][1] = fmaf(a.y, b.y, acc[1][1]);
            acc[1][2] = fmaf(a.y, b.z, acc[1][2]);
            acc[1][3] = fmaf(a.y, b.w, acc[1][3]);
        }
        if (hasNext) {
            int nb = buf ^ 1;
            As[nb][lk4 * 4 + 0][lm] = av2.x;
            As[nb][lk4 * 4 + 1][lm] = av2.y;
            As[nb][lk4 * 4 + 2][lm] = av2.z;
            As[nb][lk4 * 4 + 3][lm] = av2.w;
            Bs[nb][bkr][bnc * 2 + 0] = bv2.x;
            Bs[nb][bkr][bnc * 2 + 1] = bv2.y;
            __syncthreads();
            buf = nb;
        }
    }

#pragma unroll
    for (int i = 0; i < 2; i++) {
        int gm = m0 + ty * 2 + i;
        if (gm < M) {
#pragma unroll
            for (int j = 0; j < 4; j++)
                atomicAdd(&C[(size_t)gm * N + n0 + tx * 4 + j], acc[i][j]);
        }
    }
}

// ---------------------------------------------------------------------------
// attn_pass: PASS2 fuses shifted coverage cumsum in prologue; PASS1 zeroes
// the loss slot AND the ctx output (for gemm_ctx atomics).
// ---------------------------------------------------------------------------
template <bool PASS2>
__global__ __launch_bounds__(NTH, 3) void attn_pass(
    const unsigned char* __restrict__ mask,
    const float* __restrict__ v,
    const float* __restrict__ wc,
    float* __restrict__ AoutParam,
    float* __restrict__ loss,
    float* __restrict__ ctxZero)
{
    __shared__ float2 sVW[H_];        // (v[h], wc[h])
    __shared__ float2 sWp[H_];        // (ws_t0[h], ws_t1[h])
    __shared__ float  sRed[48];

    int tid = threadIdx.x;
    int b   = blockIdx.x / (T_ / TGT);
    int t0  = (blockIdx.x % (T_ / TGT)) * TGT;

    if (!PASS2) {
        // zero ctx: 400 CTAs x 512 floats == B*T*H == 204800 exactly
        size_t base = (size_t)blockIdx.x * 512;
        for (int i = tid; i < 512; i += NTH) ctxZero[base + i] = 0.f;
        if (blockIdx.x == 0 && tid == 0) *loss = 0.f;
    }

    const float* ws0 = g_Ws + ((size_t)b * T_ + t0) * H_;
    for (int h = tid; h < H_; h += NTH) {
        sVW[h] = make_float2(v[h], PASS2 ? wc[h] : 0.f);
        sWp[h] = make_float2(ws0[h], ws0[H_ + h]);
    }
    __syncthreads();

    size_t row0 = ((size_t)b * T_ + t0) * S_;
    size_t row1 = row0 + S_;

    int s = tid;
    float ex0 = 0.f, ex1 = 0.f;
    float c0 = 0.f, c1 = 0.f;
    if (s < S_) {
        const float* whp = g_WhT + (size_t)b * H_ * S_ + s;
        bool mk = mask[b * S_ + s] != 0;

        if (PASS2) {
            // fused shifted cumsum: c0 = sum_{t'<t0} Apre, c1 = c0 + Apre[t0]
            const float* ap = g_Apre + (size_t)b * T_ * S_ + s;
            float sum = 0.f;
            int t = 0;
            for (; t + 4 <= t0; t += 4) {
                float a0 = __ldg(ap + (size_t)t * S_);
                float a1 = __ldg(ap + (size_t)(t + 1) * S_);
                float a2 = __ldg(ap + (size_t)(t + 2) * S_);
                float a3 = __ldg(ap + (size_t)(t + 3) * S_);
                sum += (a0 + a1) + (a2 + a3);
            }
            for (; t < t0; t++) sum += __ldg(ap + (size_t)t * S_);
            c0 = sum;
            c1 = sum + __ldg(ap + (size_t)t0 * S_);
        }

        float acc0 = 0.f, acc1 = 0.f;

        // rotating scalar prefetch, depth 4; branchless tail (clamped index)
        float p0 = __ldg(whp);
        float p1 = __ldg(whp + S_);
        float p2 = __ldg(whp + 2 * S_);
        float p3 = __ldg(whp + 3 * S_);

#pragma unroll 2
        for (int h0 = 0; h0 < H_; h0 += 4) {
            int hn = (h0 + 4 < H_) ? (h0 + 4) : 0;   // SEL, no branch
            const float* q = whp + (size_t)hn * S_;
            float n0 = __ldg(q);
            float n1 = __ldg(q + S_);
            float n2 = __ldg(q + 2 * S_);
            float n3 = __ldg(q + 3 * S_);
#pragma unroll
            for (int i = 0; i < 4; i++) {
                float whv = (i == 0) ? p0 : (i == 1) ? p1 : (i == 2) ? p2 : p3;
                int h = h0 + i;
                float2 vw = sVW[h];
                float2 wp = sWp[h];
                float x0 = whv + wp.x;
                float x1 = whv + wp.y;
                if (PASS2) {
                    x0 = fmaf(c0, vw.y, x0);
                    x1 = fmaf(c1, vw.y, x1);
                }
                __half2 xh = __floats2half2_rn(x0, x1);
                unsigned th = tanh2(*(unsigned*)&xh);
                __half2 t2 = *(__half2*)&th;
                acc0 = fmaf(vw.x, __low2float(t2),  acc0);
                acc1 = fmaf(vw.x, __high2float(t2), acc1);
            }
            p0 = n0; p1 = n1; p2 = n2; p3 = n3;
        }

        float e0 = fminf(fmaxf(acc0, -30.0f), 30.0f);
        float e1 = fminf(fmaxf(acc1, -30.0f), 30.0f);
        // fixed max = 30 (clip upper bound) -> exp in [e^-60, 1], masked -> 0
        ex0 = mk ? 0.f : __expf(e0 - 30.0f);
        ex1 = mk ? 0.f : __expf(e1 - 30.0f);
    }

    // fused dual-sum reduction (2 syncs)
    int lane = tid & 31, wid = tid >> 5;  // 13 warps
    float s0 = ex0, s1 = ex1;
#pragma unroll
    for (int o = 16; o; o >>= 1) {
        s0 += __shfl_xor_sync(0xffffffffu, s0, o);
        s1 += __shfl_xor_sync(0xffffffffu, s1, o);
    }
    if (lane == 0) { sRed[wid] = s0; sRed[16 + wid] = s1; }
    __syncthreads();
    if (wid == 0) {
        float a0 = (lane < 13) ? sRed[lane]      : 0.f;
        float a1 = (lane < 13) ? sRed[16 + lane] : 0.f;
#pragma unroll
        for (int o = 16; o; o >>= 1) {
            a0 += __shfl_xor_sync(0xffffffffu, a0, o);
            a1 += __shfl_xor_sync(0xffffffffu, a1, o);
        }
        if (lane == 0) { sRed[32] = a0; sRed[33] = a1; }
    }
    __syncthreads();
    float inv0 = 1.0f / fmaxf(sRed[32], 1e-30f);
    float inv1 = 1.0f / fmaxf(sRed[33], 1e-30f);

    float lossAcc = 0.f;
    if (s < S_) {
        float a0 = ex0 * inv0;
        float a1 = ex1 * inv1;
        float* out0 = (PASS2 ? AoutParam : g_Apre);
        out0[row0 + s] = a0;
        out0[row1 + s] = a1;
        if (PASS2) lossAcc = fminf(a0, c0) + fminf(a1, c1);
    }

    if (PASS2) {
        __syncthreads();  // protect sRed reuse
#pragma unroll
        for (int o = 16; o; o >>= 1) lossAcc += __shfl_xor_sync(0xffffffffu, lossAcc, o);
        if (lane == 0) sRed[wid] = lossAcc;
        __syncthreads();
        if (tid == 0) {
            float p = 0.f;
#pragma unroll
            for (int i = 0; i < 13; i++) p += sRed[i];
            atomicAdd(loss, p * (1.0f / (B_ * T_)));
        }
    }
}

// ---------------------------------------------------------------------------
extern "C" void kernel_launch(void* const* d_in, const int* in_sizes, int n_in,
                              void* d_out, int out_size)
{
    const float*         dec    = (const float*)d_in[0];
    const float*         enc    = (const float*)d_in[1];
    const unsigned char* mask   = (const unsigned char*)d_in[2];
    const float*         W_h    = (const float*)d_in[3];
    const float*         W_s    = (const float*)d_in[4];
    const float*         w_c    = (const float*)d_in[5];
    const float*         v      = (const float*)d_in[6];
    const float*         b_attn = (const float*)d_in[7];

    float* out  = (float*)d_out;
    float* ctx  = out;
    float* Afin = out + (size_t)B_ * T_ * H_;
    float* loss = Afin + (size_t)B_ * T_ * S_;

    // Fused projections: 50 WhT tiles + 13 Ws tiles -> grid (8, 63)
    dual_gemm<<<dim3(H_ / 32, 63), 256>>>(enc, W_h, dec, W_s, b_attn);

    // Pass 1: A_prelim (also zeroes loss slot + ctx for the atomics)
    attn_pass<false><<<B_ * (T_ / TGT), NTH>>>(mask, v, nullptr, nullptr, loss, ctx);

    // Pass 2: A_final + cov_loss (cumsum fused into prologue)
    attn_pass<true><<<B_ * (T_ / TGT), NTH>>>(mask, v, w_c, Afin, loss, nullptr);

    // context[b] = A_final[b] @ enc[b]  (split-K=2, atomic combine)
    gemm_ctx<<<dim3(H_ / 32, (T_ + 63) / 64, B_ * 2), 256>>>(
        Afin, enc, ctx, T_, H_, S_,
        (long long)T_ * S_, (long long)S_ * H_, (long long)T_ * H_);
}